// round 2
// baseline (speedup 1.0000x reference)
#include <cuda_runtime.h>
#include <math.h>
#include <stdint.h>

#define B_   32
#define T_   256
#define IN_  512
#define H_   512
#define G4   2048   /* 4*H */
#define NREC_CTAS 128

/* ------------------------------------------------------------------ */
/* Static device scratch (no runtime allocation allowed)              */
/* ------------------------------------------------------------------ */
__device__ float g_xgF[(size_t)T_ * B_ * G4];          /* 64 MB  */
__device__ float g_xgB[(size_t)T_ * B_ * G4];          /* 64 MB  */
__device__ float g_out0[(size_t)B_ * T_ * 2 * H_];     /* 32 MB  */
__device__ float g_Wt[4][(size_t)G4 * H_];             /* 16 MB: W_hh transposed [col][k] */
__device__ float g_h[2][2][B_ * H_];                   /* [dir][parity][b*H+h] */
__device__ unsigned g_barCount;
__device__ unsigned g_barGen;

/* ------------------------------------------------------------------ */
/* Grid-wide software barrier (all CTAs resident: 128 CTAs, 148 SMs,  */
/* 1 CTA/SM occupancy guaranteed by launch_bounds + smem opt-in)      */
/* ------------------------------------------------------------------ */
__device__ __forceinline__ void grid_barrier()
{
    __threadfence();          /* publish this thread's global writes   */
    __syncthreads();
    if (threadIdx.x == 0) {
        unsigned gen = *((volatile unsigned*)&g_barGen);
        unsigned arrived = atomicAdd(&g_barCount, 1u);
        if (arrived == gridDim.x - 1) {
            atomicExch(&g_barCount, 0u);      /* reset BEFORE release  */
            __threadfence();
            atomicAdd(&g_barGen, 1u);         /* release */
        } else {
            while (*((volatile unsigned*)&g_barGen) == gen) {
                __nanosleep(64);
            }
        }
    }
    __syncthreads();
    __threadfence();
}

__device__ __forceinline__ float sigmoidf_(float x)
{
    return 1.0f / (1.0f + expf(-x));
}

/* ------------------------------------------------------------------ */
/* Transpose W_hh [H, 4H] -> Wt [4H, H]  (Wt[col][k] = W[k][col])     */
/* ------------------------------------------------------------------ */
__global__ void transpose_whh(const float* __restrict__ W, float* __restrict__ Wt)
{
    __shared__ float tile[32][33];
    int x  = blockIdx.x * 32 + threadIdx.x;   /* col in W  */
    int y0 = blockIdx.y * 32;                 /* k base    */
    #pragma unroll
    for (int i = threadIdx.y; i < 32; i += 8)
        tile[i][threadIdx.x] = W[(size_t)(y0 + i) * G4 + x];
    __syncthreads();
    int k  = y0 + threadIdx.x;
    int c0 = blockIdx.x * 32;
    #pragma unroll
    for (int i = threadIdx.y; i < 32; i += 8)
        Wt[(size_t)(c0 + i) * H_ + k] = tile[threadIdx.x][i];
}

/* ------------------------------------------------------------------ */
/* Input GEMM: xg[t*B+b][col] = sum_i A[b][t][i] * W[i][col] + bias   */
/* A layout [B, T, Din] row-major. out layout [M=T*B, 4H].            */
/* Tile 128x128x8, 256 threads, 8x8 microtile.                        */
/* ------------------------------------------------------------------ */
__global__ void __launch_bounds__(256)
gemm_xg_kernel(const float* __restrict__ A, const float* __restrict__ W,
               const float* __restrict__ bias, float* __restrict__ out, int Din)
{
    __shared__ float As[8][128];
    __shared__ float Bs[8][128];
    const int tx   = threadIdx.x & 15;
    const int ty   = threadIdx.x >> 4;
    const int row0 = blockIdx.y * 128;
    const int col0 = blockIdx.x * 128;

    /* A loader: row a_r of tile, 4 consecutive k */
    const int a_r = threadIdx.x >> 1;
    const int a_k = (threadIdx.x & 1) * 4;
    const int m   = row0 + a_r;                       /* m = t*B + b */
    const float* a_src = A + (size_t)((m & 31) * T_ + (m >> 5)) * Din + a_k;

    /* B loader: row b_k, 4 consecutive cols */
    const int b_k = threadIdx.x >> 5;
    const int b_c = (threadIdx.x & 31) * 4;
    const float* b_src = W + (size_t)b_k * G4 + col0 + b_c;

    float acc[8][8];
    #pragma unroll
    for (int i = 0; i < 8; i++)
        #pragma unroll
        for (int j = 0; j < 8; j++) acc[i][j] = 0.0f;

    for (int kb = 0; kb < Din; kb += 8) {
        float4 av = *(const float4*)(a_src + kb);
        float4 bv = *(const float4*)(b_src + (size_t)kb * G4);
        As[a_k + 0][a_r] = av.x;
        As[a_k + 1][a_r] = av.y;
        As[a_k + 2][a_r] = av.z;
        As[a_k + 3][a_r] = av.w;
        *(float4*)&Bs[b_k][b_c] = bv;
        __syncthreads();
        #pragma unroll
        for (int k = 0; k < 8; k++) {
            float ar[8], br[8];
            #pragma unroll
            for (int i = 0; i < 8; i++) ar[i] = As[k][ty * 8 + i];
            #pragma unroll
            for (int j = 0; j < 8; j++) br[j] = Bs[k][tx * 8 + j];
            #pragma unroll
            for (int i = 0; i < 8; i++)
                #pragma unroll
                for (int j = 0; j < 8; j++)
                    acc[i][j] += ar[i] * br[j];
        }
        __syncthreads();
    }

    #pragma unroll
    for (int i = 0; i < 8; i++) {
        int r = row0 + ty * 8 + i;
        #pragma unroll
        for (int j = 0; j < 8; j++) {
            int cidx = col0 + tx * 8 + j;
            out[(size_t)r * G4 + cidx] = acc[i][j] + __ldg(&bias[cidx]);
        }
    }
}

/* ------------------------------------------------------------------ */
/* Persistent bidirectional LSTM recurrence (one layer).              */
/* 128 CTAs: CTA 0..63 forward, 64..127 backward. 256 threads.        */
/* Warp w owns hidden index hid = (cta%64)*8 + w; lane = batch b.     */
/* Each thread owns one (b, hid): c lives in a register all T steps.  */
/* Per step: g = xg[t] + h_prev @ W_hh  -> gates -> c,h update.       */
/* h double-buffered in global (stcg/ldcg), staged via padded SMEM.   */
/* ------------------------------------------------------------------ */
__global__ void __launch_bounds__(256, 1)
lstm_rec_kernel(const float* __restrict__ xgF, const float* __restrict__ xgB,
                const float* __restrict__ WtF, const float* __restrict__ WtB,
                float* __restrict__ out)
{
    extern __shared__ float h_s[];            /* [32][516] padded, 66048 B */
    const int dir  = blockIdx.x >> 6;
    const int dd   = blockIdx.x & 63;
    const int warp = threadIdx.x >> 5;
    const int b    = threadIdx.x & 31;
    const int hid  = dd * 8 + warp;

    const float* xg = dir ? xgB : xgF;
    const float* Wt = dir ? WtB : WtF;
    /* 4 gate weight rows (uniform across warp): Wt[(g*H + hid)][k] */
    const float4* w0 = (const float4*)(Wt + (size_t)(0 * H_ + hid) * H_);
    const float4* w1 = (const float4*)(Wt + (size_t)(1 * H_ + hid) * H_);
    const float4* w2 = (const float4*)(Wt + (size_t)(2 * H_ + hid) * H_);
    const float4* w3 = (const float4*)(Wt + (size_t)(3 * H_ + hid) * H_);

    float c = 0.0f;
    float* hw0 = &g_h[dir][0][b * H_ + hid];
    float* hw1 = &g_h[dir][1][b * H_ + hid];

    for (int s = 0; s < T_; s++) {
        const int t = dir ? (T_ - 1 - s) : s;
        const float* xrow = xg + (size_t)(t * B_ + b) * G4 + hid;
        float a0 = xrow[0];
        float a1 = xrow[H_];
        float a2 = xrow[2 * H_];
        float a3 = xrow[3 * H_];

        if (s > 0) {
            /* stage previous h (L2-coherent) into padded SMEM */
            const float4* hsrc = (const float4*)g_h[dir][(s - 1) & 1];
            for (int idx = threadIdx.x; idx < (B_ * H_ / 4); idx += 256) {
                int bb = idx >> 7;
                int kc = idx & 127;
                float4 v = __ldcg(hsrc + idx);
                *(float4*)&h_s[bb * 516 + kc * 4] = v;
            }
            __syncthreads();

            const float4* hp = (const float4*)&h_s[b * 516];
            #pragma unroll 8
            for (int kc = 0; kc < 128; kc++) {
                float4 hv = hp[kc];
                float4 wa = __ldg(w0 + kc);
                float4 wb = __ldg(w1 + kc);
                float4 wc = __ldg(w2 + kc);
                float4 wd = __ldg(w3 + kc);
                a0 += hv.x * wa.x + hv.y * wa.y + hv.z * wa.z + hv.w * wa.w;
                a1 += hv.x * wb.x + hv.y * wb.y + hv.z * wb.z + hv.w * wb.w;
                a2 += hv.x * wc.x + hv.y * wc.y + hv.z * wc.z + hv.w * wc.w;
                a3 += hv.x * wd.x + hv.y * wd.y + hv.z * wd.z + hv.w * wd.w;
            }
        }

        float ig = sigmoidf_(a0);
        float fg = sigmoidf_(a1);
        float gg = tanhf(a2);
        float og = sigmoidf_(a3);
        c = fg * c + ig * gg;
        float h = og * tanhf(c);

        out[(size_t)(b * T_ + t) * (2 * H_) + dir * H_ + hid] = h;
        __stcg((s & 1) ? hw1 : hw0, h);

        if (s != T_ - 1) grid_barrier();
    }
}

/* ------------------------------------------------------------------ */
/* Host launcher                                                      */
/* ------------------------------------------------------------------ */
extern "C" void kernel_launch(void* const* d_in, const int* in_sizes, int n_in,
                              void* d_out, int out_size)
{
    const float* x     = (const float*)d_in[0];
    const float* wih0f = (const float*)d_in[1];
    const float* whh0f = (const float*)d_in[2];
    const float* b0f   = (const float*)d_in[3];
    const float* wih0b = (const float*)d_in[4];
    const float* whh0b = (const float*)d_in[5];
    const float* b0b   = (const float*)d_in[6];
    const float* wih1f = (const float*)d_in[7];
    const float* whh1f = (const float*)d_in[8];
    const float* b1f   = (const float*)d_in[9];
    const float* wih1b = (const float*)d_in[10];
    const float* whh1b = (const float*)d_in[11];
    const float* b1b   = (const float*)d_in[12];

    float *xgF, *xgB, *out0, *wt;
    cudaGetSymbolAddress((void**)&xgF,  g_xgF);
    cudaGetSymbolAddress((void**)&xgB,  g_xgB);
    cudaGetSymbolAddress((void**)&out0, g_out0);
    cudaGetSymbolAddress((void**)&wt,   g_Wt);

    cudaFuncSetAttribute(lstm_rec_kernel,
                         cudaFuncAttributeMaxDynamicSharedMemorySize, 66048);

    dim3 tb(32, 8);
    dim3 tg(G4 / 32, H_ / 32);                 /* (64, 16) */
    transpose_whh<<<tg, tb>>>(whh0f, wt + 0 * (size_t)G4 * H_);
    transpose_whh<<<tg, tb>>>(whh0b, wt + 1 * (size_t)G4 * H_);
    transpose_whh<<<tg, tb>>>(whh1f, wt + 2 * (size_t)G4 * H_);
    transpose_whh<<<tg, tb>>>(whh1b, wt + 3 * (size_t)G4 * H_);

    dim3 gg(G4 / 128, (T_ * B_) / 128);        /* (16, 64) */

    /* layer 0 input GEMMs */
    gemm_xg_kernel<<<gg, 256>>>(x, wih0f, b0f, xgF, IN_);
    gemm_xg_kernel<<<gg, 256>>>(x, wih0b, b0b, xgB, IN_);
    /* layer 0 recurrence -> g_out0 */
    lstm_rec_kernel<<<NREC_CTAS, 256, 66048>>>(
        xgF, xgB, wt + 0 * (size_t)G4 * H_, wt + 1 * (size_t)G4 * H_, out0);
    /* layer 1 input GEMMs (Din = 2H) */
    gemm_xg_kernel<<<gg, 256>>>(out0, wih1f, b1f, xgF, 2 * H_);
    gemm_xg_kernel<<<gg, 256>>>(out0, wih1b, b1b, xgB, 2 * H_);
    /* layer 1 recurrence -> final output */
    lstm_rec_kernel<<<NREC_CTAS, 256, 66048>>>(
        xgF, xgB, wt + 2 * (size_t)G4 * H_, wt + 3 * (size_t)G4 * H_,
        (float*)d_out);
}

// round 6
// speedup vs baseline: 1.4276x; 1.4276x over previous
#include <cuda_runtime.h>
#include <math.h>
#include <stdint.h>

#define B_   32
#define T_   256
#define IN_  512
#define H_   512
#define G4   2048   /* 4*H */
#define NREC_CTAS 128

/* ------------------------------------------------------------------ */
/* Static device scratch                                              */
/* ------------------------------------------------------------------ */
__device__ float g_xgF[(size_t)T_ * B_ * G4];          /* 64 MB, layout [t][col][b] */
__device__ float g_xgB[(size_t)T_ * B_ * G4];          /* 64 MB, layout [t][col][b] */
__device__ float g_out0[(size_t)B_ * T_ * 2 * H_];     /* 32 MB, layout [b][t][2H]  */
__device__ float g_Wt[4][(size_t)G4 * H_];             /* 16 MB: W_hh transposed [4H][H] */
__device__ float g_h[2][2][B_ * H_];                   /* [dir][parity][b*H+h] */
__device__ unsigned g_barCount;
__device__ unsigned g_barGen;

/* ------------------------------------------------------------------ */
/* Grid-wide software barrier (128 CTAs co-resident on 148 SMs)       */
/* ------------------------------------------------------------------ */
__device__ __forceinline__ void grid_barrier()
{
    __threadfence();
    __syncthreads();
    if (threadIdx.x == 0) {
        unsigned gen = *((volatile unsigned*)&g_barGen);
        unsigned arrived = atomicAdd(&g_barCount, 1u);
        if (arrived == gridDim.x - 1) {
            atomicExch(&g_barCount, 0u);
            __threadfence();
            atomicAdd(&g_barGen, 1u);
        } else {
            while (*((volatile unsigned*)&g_barGen) == gen) {
                __nanosleep(64);
            }
        }
    }
    __syncthreads();
    __threadfence();
}

__device__ __forceinline__ float sigmoidf_(float x)
{
    return 1.0f / (1.0f + expf(-x));
}

/* ------------------------------------------------------------------ */
/* Transpose W_hh [H, 4H] -> Wt [4H, H]  (Wt[col][k] = W[k][col])     */
/* ------------------------------------------------------------------ */
__global__ void transpose_whh(const float* __restrict__ W, float* __restrict__ Wt)
{
    __shared__ float tile[32][33];
    int x  = blockIdx.x * 32 + threadIdx.x;   /* col in W  */
    int y0 = blockIdx.y * 32;                 /* k base    */
    #pragma unroll
    for (int i = threadIdx.y; i < 32; i += 8)
        tile[i][threadIdx.x] = W[(size_t)(y0 + i) * G4 + x];
    __syncthreads();
    int k  = y0 + threadIdx.x;
    int c0 = blockIdx.x * 32;
    #pragma unroll
    for (int i = threadIdx.y; i < 32; i += 8)
        Wt[(size_t)(c0 + i) * H_ + k] = tile[threadIdx.x][i];
}

/* ------------------------------------------------------------------ */
/* Input GEMM: computes xg = A @ W + bias for all timesteps.          */
/* A layout [B, T, Din] row-major (m = t*B + b reads A[b][t][:]).     */
/* OUTPUT LAYOUT: out[(t*4H + col)*32 + b]  (batch-contiguous so the  */
/* recurrence reads coalesced).                                       */
/* Tile 128x128x16, 256 threads, 8x8 microtile, SMEM double-buffer    */
/* with register prefetch (one __syncthreads per k-tile).             */
/* ------------------------------------------------------------------ */
__global__ void __launch_bounds__(256)
gemm_xg_kernel(const float* __restrict__ A, const float* __restrict__ W,
               const float* __restrict__ bias, float* __restrict__ out, int Din)
{
    __shared__ float As[2][16][128];
    __shared__ float Bs[2][16][128];
    const int tid  = threadIdx.x;
    const int tx   = tid & 15;
    const int ty   = tid >> 4;
    const int row0 = blockIdx.y * 128;
    const int col0 = blockIdx.x * 128;

    /* A loader: row ar_row of tile, k-span [ar_k0, ar_k0+8)          */
    const int ar_row = tid >> 1;
    const int ar_k0  = (tid & 1) * 8;
    const int m      = row0 + ar_row;                /* m = t*B + b   */
    const float* a_src = A + (size_t)((m & 31) * T_ + (m >> 5)) * Din + ar_k0;

    /* B loader: k row bk, cols [bc, bc+8)                            */
    const int bk = tid >> 4;                          /* 0..15        */
    const int bc = (tid & 15) * 8;                    /* 0..120       */
    const float* b_src = W + (size_t)bk * G4 + col0 + bc;

    float acc[8][8];
    #pragma unroll
    for (int i = 0; i < 8; i++)
        #pragma unroll
        for (int j = 0; j < 8; j++) acc[i][j] = 0.0f;

    /* prologue: load tile 0 into registers, park in buffer 0 */
    float4 va0 = *(const float4*)(a_src);
    float4 va1 = *(const float4*)(a_src + 4);
    float4 vb0 = *(const float4*)(b_src);
    float4 vb1 = *(const float4*)(b_src + 4);

    As[0][ar_k0 + 0][ar_row] = va0.x;  As[0][ar_k0 + 1][ar_row] = va0.y;
    As[0][ar_k0 + 2][ar_row] = va0.z;  As[0][ar_k0 + 3][ar_row] = va0.w;
    As[0][ar_k0 + 4][ar_row] = va1.x;  As[0][ar_k0 + 5][ar_row] = va1.y;
    As[0][ar_k0 + 6][ar_row] = va1.z;  As[0][ar_k0 + 7][ar_row] = va1.w;
    *(float4*)&Bs[0][bk][bc]     = vb0;
    *(float4*)&Bs[0][bk][bc + 4] = vb1;
    __syncthreads();

    const int Nk = Din >> 4;
    for (int kt = 0; kt < Nk; kt++) {
        const int cur = kt & 1;
        const int nxt = cur ^ 1;

        if (kt + 1 < Nk) {
            const int kb = (kt + 1) << 4;
            va0 = *(const float4*)(a_src + kb);
            va1 = *(const float4*)(a_src + kb + 4);
            vb0 = *(const float4*)(b_src + (size_t)kb * G4);
            vb1 = *(const float4*)(b_src + (size_t)kb * G4 + 4);
        }

        #pragma unroll
        for (int k = 0; k < 16; k++) {
            float4 a0 = *(const float4*)&As[cur][k][ty * 8];
            float4 a1 = *(const float4*)&As[cur][k][ty * 8 + 4];
            float4 b0 = *(const float4*)&Bs[cur][k][tx * 8];
            float4 b1 = *(const float4*)&Bs[cur][k][tx * 8 + 4];
            float af[8] = {a0.x, a0.y, a0.z, a0.w, a1.x, a1.y, a1.z, a1.w};
            float bf[8] = {b0.x, b0.y, b0.z, b0.w, b1.x, b1.y, b1.z, b1.w};
            #pragma unroll
            for (int i = 0; i < 8; i++)
                #pragma unroll
                for (int j = 0; j < 8; j++)
                    acc[i][j] += af[i] * bf[j];
        }

        if (kt + 1 < Nk) {
            As[nxt][ar_k0 + 0][ar_row] = va0.x;  As[nxt][ar_k0 + 1][ar_row] = va0.y;
            As[nxt][ar_k0 + 2][ar_row] = va0.z;  As[nxt][ar_k0 + 3][ar_row] = va0.w;
            As[nxt][ar_k0 + 4][ar_row] = va1.x;  As[nxt][ar_k0 + 5][ar_row] = va1.y;
            As[nxt][ar_k0 + 6][ar_row] = va1.z;  As[nxt][ar_k0 + 7][ar_row] = va1.w;
            *(float4*)&Bs[nxt][bk][bc]     = vb0;
            *(float4*)&Bs[nxt][bk][bc + 4] = vb1;
        }
        __syncthreads();
    }

    /* Epilogue: transposed store out[(t*4H + col)*32 + b].
       rows r = row0+ty*8+i share t0 = r>>5 and have b = b0+i
       (b0 = (ty*8)&31, multiple of 8 => i stays inside one t-block,
       and consecutive i are consecutive addresses => float4 stores). */
    const int rbase = row0 + ty * 8;
    const int t0 = rbase >> 5;
    const int b0 = rbase & 31;
    #pragma unroll
    for (int j = 0; j < 8; j++) {
        const int cidx = col0 + tx * 8 + j;
        const float bj = __ldg(&bias[cidx]);
        float* dst = out + ((size_t)t0 * G4 + cidx) * 32 + b0;
        float4 s0 = make_float4(acc[0][j] + bj, acc[1][j] + bj,
                                acc[2][j] + bj, acc[3][j] + bj);
        float4 s1 = make_float4(acc[4][j] + bj, acc[5][j] + bj,
                                acc[6][j] + bj, acc[7][j] + bj);
        *(float4*)(dst)     = s0;
        *(float4*)(dst + 4) = s1;
    }
}

/* ------------------------------------------------------------------ */
/* Persistent bidirectional LSTM recurrence (one layer).              */
/* 128 CTAs (0..63 fwd, 64..127 bwd), 256 threads.                    */
/* Warp wl owns hid = dd*8 + wl; lane = batch b.                      */
/* Weights live in SMEM (loaded once: 8 hids x 4 gates x 512 floats = */
/* 64 KB, read as warp-uniform broadcast LDS). h staged in SMEM with  */
/* 516-float row stride (conflict-free float4 phases). c in register. */
/* xg layout [t][col][b] -> fully coalesced loads.                    */
/* ------------------------------------------------------------------ */
__global__ void __launch_bounds__(256, 1)
lstm_rec_kernel(const float* __restrict__ xgF, const float* __restrict__ xgB,
                const float* __restrict__ WtF, const float* __restrict__ WtB,
                float* __restrict__ out)
{
    extern __shared__ float sm[];
    float* w_s = sm;                       /* 16384 floats = 64 KB       */
    float* h_s = sm + 16384;               /* 32 rows * 516 floats       */

    const int tid = threadIdx.x;
    const int dir = blockIdx.x >> 6;
    const int dd  = blockIdx.x & 63;
    const int wl  = tid >> 5;              /* local hid 0..7             */
    const int b   = tid & 31;
    const int hid = dd * 8 + wl;

    const float* xg = dir ? xgB : xgF;
    const float* Wt = dir ? WtB : WtF;

    /* Load this CTA's 8 hids' weights into SMEM once.
       dst w_s[wl*2048 + g*512 + k]; src Wt[(g*H + dd*8+wl)*H + k].    */
    for (int i = tid; i < 4096; i += 256) {          /* float4 units    */
        int dwl = i >> 9;                            /* 0..7            */
        int g   = (i >> 7) & 3;
        int kc  = i & 127;
        float4 v = __ldg((const float4*)Wt +
                         ((size_t)(g * H_ + dd * 8 + dwl) * H_ / 4) + kc);
        *((float4*)w_s + (size_t)dwl * 512 + g * 128 + kc) = v;
    }
    __syncthreads();

    const float4* wg0 = (const float4*)(w_s + wl * 2048);
    const float4* wg1 = wg0 + 128;
    const float4* wg2 = wg0 + 256;
    const float4* wg3 = wg0 + 384;
    const float4* hp  = (const float4*)(h_s + b * 516);

    float c = 0.0f;
    float* hw0 = &g_h[dir][0][b * H_ + hid];
    float* hw1 = &g_h[dir][1][b * H_ + hid];

    for (int s = 0; s < T_; s++) {
        const int t = dir ? (T_ - 1 - s) : s;
        const float* xr = xg + ((size_t)t * G4 + hid) * 32 + b;
        float a0 = xr[0 * H_ * 32];
        float a1 = xr[1 * H_ * 32];
        float a2 = xr[2 * H_ * 32];
        float a3 = xr[3 * H_ * 32];

        if (s > 0) {
            /* stage previous h (L2-coherent) into padded SMEM:
               B_*H_/4 = 4096 float4 elements total.                   */
            const float4* hsrc = (const float4*)g_h[dir][(s - 1) & 1];
            for (int idx = tid; idx < (B_ * H_ / 4); idx += 256) {
                int bb = idx >> 7;
                int kc = idx & 127;
                float4 v = __ldcg(hsrc + idx);
                *(float4*)&h_s[bb * 516 + kc * 4] = v;
            }
            __syncthreads();

            #pragma unroll 8
            for (int kc = 0; kc < 128; kc++) {
                float4 hv = hp[kc];
                float4 wa = wg0[kc];
                float4 wb = wg1[kc];
                float4 wc = wg2[kc];
                float4 wd = wg3[kc];
                a0 += hv.x * wa.x + hv.y * wa.y + hv.z * wa.z + hv.w * wa.w;
                a1 += hv.x * wb.x + hv.y * wb.y + hv.z * wb.z + hv.w * wb.w;
                a2 += hv.x * wc.x + hv.y * wc.y + hv.z * wc.z + hv.w * wc.w;
                a3 += hv.x * wd.x + hv.y * wd.y + hv.z * wd.z + hv.w * wd.w;
            }
        }

        float ig = sigmoidf_(a0);
        float fg = sigmoidf_(a1);
        float gg = tanhf(a2);
        float og = sigmoidf_(a3);
        c = fg * c + ig * gg;
        float h = og * tanhf(c);

        out[(size_t)(b * T_ + t) * (2 * H_) + dir * H_ + hid] = h;
        __stcg((s & 1) ? hw1 : hw0, h);

        if (s != T_ - 1) grid_barrier();
    }
}

/* ------------------------------------------------------------------ */
/* Host launcher                                                      */
/* ------------------------------------------------------------------ */
extern "C" void kernel_launch(void* const* d_in, const int* in_sizes, int n_in,
                              void* d_out, int out_size)
{
    const float* x     = (const float*)d_in[0];
    const float* wih0f = (const float*)d_in[1];
    const float* whh0f = (const float*)d_in[2];
    const float* b0f   = (const float*)d_in[3];
    const float* wih0b = (const float*)d_in[4];
    const float* whh0b = (const float*)d_in[5];
    const float* b0b   = (const float*)d_in[6];
    const float* wih1f = (const float*)d_in[7];
    const float* whh1f = (const float*)d_in[8];
    const float* b1f   = (const float*)d_in[9];
    const float* wih1b = (const float*)d_in[10];
    const float* whh1b = (const float*)d_in[11];
    const float* b1b   = (const float*)d_in[12];

    float *xgF, *xgB, *out0, *wt;
    cudaGetSymbolAddress((void**)&xgF,  g_xgF);
    cudaGetSymbolAddress((void**)&xgB,  g_xgB);
    cudaGetSymbolAddress((void**)&out0, g_out0);
    cudaGetSymbolAddress((void**)&wt,   g_Wt);

    const size_t WSET = (size_t)G4 * H_;
    const int REC_SMEM = 65536 + 32 * 516 * 4;     /* 131584 B */
    cudaFuncSetAttribute(lstm_rec_kernel,
                         cudaFuncAttributeMaxDynamicSharedMemorySize, REC_SMEM);

    dim3 tb(32, 8);
    dim3 tg(G4 / 32, H_ / 32);                 /* (64, 16) */
    transpose_whh<<<tg, tb>>>(whh0f, wt + 0 * WSET);
    transpose_whh<<<tg, tb>>>(whh0b, wt + 1 * WSET);
    transpose_whh<<<tg, tb>>>(whh1f, wt + 2 * WSET);
    transpose_whh<<<tg, tb>>>(whh1b, wt + 3 * WSET);

    dim3 gg(G4 / 128, (T_ * B_) / 128);        /* (16, 64) */

    /* layer 0 input GEMMs */
    gemm_xg_kernel<<<gg, 256>>>(x, wih0f, b0f, xgF, IN_);
    gemm_xg_kernel<<<gg, 256>>>(x, wih0b, b0b, xgB, IN_);
    /* layer 0 recurrence -> g_out0 */
    lstm_rec_kernel<<<NREC_CTAS, 256, REC_SMEM>>>(
        xgF, xgB, wt + 0 * WSET, wt + 1 * WSET, out0);
    /* layer 1 input GEMMs (Din = 2H) */
    gemm_xg_kernel<<<gg, 256>>>(out0, wih1f, b1f, xgF, 2 * H_);
    gemm_xg_kernel<<<gg, 256>>>(out0, wih1b, b1b, xgB, 2 * H_);
    /* layer 1 recurrence -> final output */
    lstm_rec_kernel<<<NREC_CTAS, 256, REC_SMEM>>>(
        xgF, xgB, wt + 2 * WSET, wt + 3 * WSET, (float*)d_out);
}

// round 8
// speedup vs baseline: 1.5719x; 1.1010x over previous
#include <cuda_runtime.h>
#include <cuda_bf16.h>
#include <mma.h>
#include <math.h>
#include <stdint.h>

using namespace nvcuda;

#define B_   32
#define T_   256
#define IN_  512
#define H_   512
#define G4   2048   /* 4*H */
#define NREC_CTAS 128

/* ------------------------------------------------------------------ */
/* Static device scratch                                              */
/* ------------------------------------------------------------------ */
__device__ float g_xgF[(size_t)T_ * B_ * G4];          /* 64 MB, [t][col][b] */
__device__ float g_xgB[(size_t)T_ * B_ * G4];          /* 64 MB, [t][col][b] */
__device__ float g_Wt[4][(size_t)G4 * H_];             /* W_hh transposed [4H][H] */
__device__ float g_h[2][2][B_ * H_];                   /* [dir][parity][b*H+h] */
__device__ unsigned g_barCount;
__device__ unsigned g_barGen;

/* bf16 hi/lo split operands for the tensor-core input GEMMs */
__device__ __nv_bfloat16 g_Ah0[(size_t)8192 * 512];    /* layer0 A hi [m][k] */
__device__ __nv_bfloat16 g_Al0[(size_t)8192 * 512];
__device__ __nv_bfloat16 g_Ah1[(size_t)8192 * 1024];   /* layer1 A hi [m][k] */
__device__ __nv_bfloat16 g_Al1[(size_t)8192 * 1024];
__device__ __nv_bfloat16 g_Wsp0[2][2][(size_t)G4 * 512];   /* [dir][hi/lo][n][k] */
__device__ __nv_bfloat16 g_Wsp1[2][2][(size_t)G4 * 1024];

/* ------------------------------------------------------------------ */
__device__ __forceinline__ void grid_barrier()
{
    __threadfence();
    __syncthreads();
    if (threadIdx.x == 0) {
        unsigned gen = *((volatile unsigned*)&g_barGen);
        unsigned arrived = atomicAdd(&g_barCount, 1u);
        if (arrived == gridDim.x - 1) {
            atomicExch(&g_barCount, 0u);
            __threadfence();
            atomicAdd(&g_barGen, 1u);
        } else {
            while (*((volatile unsigned*)&g_barGen) == gen) {
                __nanosleep(64);
            }
        }
    }
    __syncthreads();
    __threadfence();
}

__device__ __forceinline__ float sigmoidf_(float x)
{
    return 1.0f / (1.0f + expf(-x));
}

__device__ __forceinline__ void bf16_split(float v, __nv_bfloat16& h, __nv_bfloat16& l)
{
    h = __float2bfloat16(v);
    l = __float2bfloat16(v - __bfloat162float(h));
}

/* ------------------------------------------------------------------ */
/* x [B][T][IN] fp32 -> Ah/Al [m=t*B+b][k] bf16 hi/lo                 */
/* ------------------------------------------------------------------ */
__global__ void split_x_kernel(const float* __restrict__ x,
                               __nv_bfloat16* __restrict__ Ah,
                               __nv_bfloat16* __restrict__ Al)
{
    int idx = blockIdx.x * blockDim.x + threadIdx.x;   /* < 8192*512 */
    int m = idx >> 9;
    int k = idx & 511;
    int b = m & 31;
    int t = m >> 5;
    float v = x[((size_t)b * T_ + t) * IN_ + k];
    __nv_bfloat16 h, l;
    bf16_split(v, h, l);
    Ah[idx] = h;
    Al[idx] = l;
}

/* ------------------------------------------------------------------ */
/* W_ih [Din][4H] fp32 -> Wh/Wl [4H][Din] bf16 hi/lo (transposed)     */
/* ------------------------------------------------------------------ */
__global__ void transpose_split_w(const float* __restrict__ W,
                                  __nv_bfloat16* __restrict__ Wh,
                                  __nv_bfloat16* __restrict__ Wl, int Din)
{
    __shared__ float tile[32][33];
    int x  = blockIdx.x * 32 + threadIdx.x;   /* col n in W */
    int y0 = blockIdx.y * 32;                 /* k base     */
    #pragma unroll
    for (int i = threadIdx.y; i < 32; i += 8)
        tile[i][threadIdx.x] = W[(size_t)(y0 + i) * G4 + x];
    __syncthreads();
    int k  = y0 + threadIdx.x;
    int n0 = blockIdx.x * 32;
    #pragma unroll
    for (int i = threadIdx.y; i < 32; i += 8) {
        float v = tile[threadIdx.x][i];
        __nv_bfloat16 h, l;
        bf16_split(v, h, l);
        Wh[(size_t)(n0 + i) * Din + k] = h;
        Wl[(size_t)(n0 + i) * Din + k] = l;
    }
}

/* ------------------------------------------------------------------ */
/* Transpose W_hh [H, 4H] -> Wt [4H, H] (recurrence weights, fp32)    */
/* ------------------------------------------------------------------ */
__global__ void transpose_whh(const float* __restrict__ W, float* __restrict__ Wt)
{
    __shared__ float tile[32][33];
    int x  = blockIdx.x * 32 + threadIdx.x;
    int y0 = blockIdx.y * 32;
    #pragma unroll
    for (int i = threadIdx.y; i < 32; i += 8)
        tile[i][threadIdx.x] = W[(size_t)(y0 + i) * G4 + x];
    __syncthreads();
    int k  = y0 + threadIdx.x;
    int c0 = blockIdx.x * 32;
    #pragma unroll
    for (int i = threadIdx.y; i < 32; i += 8)
        Wt[(size_t)(c0 + i) * H_ + k] = tile[threadIdx.x][i];
}

/* ------------------------------------------------------------------ */
/* WMMA input GEMM, split-bf16 (3 products), fp32 accumulate.         */
/* C[m][n] = sum_k (Ah+Al)[m][k] * (Bh+Bl)[n][k]  (lo*lo dropped)     */
/* CTA tile 128x128, 8 warps of 64x32 (4x2 wmma 16x16x16 tiles),      */
/* k-tile 16, SMEM stride 24 bf16, double-buffered.                   */
/* Output layout: out[(t*4H + col)*32 + b] + bias.                    */
/* ------------------------------------------------------------------ */
__global__ void __launch_bounds__(256)
gemm_wmma_kernel(const __nv_bfloat16* __restrict__ Ah,
                 const __nv_bfloat16* __restrict__ Al,
                 const __nv_bfloat16* __restrict__ Bh,
                 const __nv_bfloat16* __restrict__ Bl,
                 const float* __restrict__ bias,
                 float* __restrict__ out, int Din)
{
    extern __shared__ char smraw[];
    __nv_bfloat16* smb = (__nv_bfloat16*)smraw;     /* 2 bufs x 4 mats x 3072 elem */
    float* csc = (float*)(smraw + 49152);           /* 8 warps x 320 floats        */

    const int tid  = threadIdx.x;
    const int lane = tid & 31;
    const int wid  = tid >> 5;
    const int wm   = wid >> 2;                 /* 0..1 */
    const int wn   = wid & 3;                  /* 0..3 */
    const int m0   = blockIdx.y * 128;
    const int col0 = blockIdx.x * 128;

    /* global loaders: row lr, 8-bf16 half lh */
    const int lr = tid >> 1;
    const int lh = tid & 1;
    const __nv_bfloat16* gAh = Ah + (size_t)(m0 + lr) * Din + lh * 8;
    const __nv_bfloat16* gAl = Al + (size_t)(m0 + lr) * Din + lh * 8;
    const __nv_bfloat16* gBh = Bh + (size_t)(col0 + lr) * Din + lh * 8;
    const __nv_bfloat16* gBl = Bl + (size_t)(col0 + lr) * Din + lh * 8;
    const int soff = lr * 24 + lh * 8;

    wmma::fragment<wmma::accumulator, 16, 16, 16, float> acc[4][2];
    #pragma unroll
    for (int i = 0; i < 4; i++)
        #pragma unroll
        for (int j = 0; j < 2; j++)
            wmma::fill_fragment(acc[i][j], 0.0f);

    uint4 rAh = *(const uint4*)gAh;
    uint4 rAl = *(const uint4*)gAl;
    uint4 rBh = *(const uint4*)gBh;
    uint4 rBl = *(const uint4*)gBl;

    *(uint4*)(smb + 0 * 12288 + 0 * 3072 + soff) = rAh;
    *(uint4*)(smb + 0 * 12288 + 1 * 3072 + soff) = rAl;
    *(uint4*)(smb + 0 * 12288 + 2 * 3072 + soff) = rBh;
    *(uint4*)(smb + 0 * 12288 + 3 * 3072 + soff) = rBl;
    __syncthreads();

    const int Nk = Din >> 4;
    for (int kt = 0; kt < Nk; kt++) {
        const int cur = kt & 1;
        const int nxt = cur ^ 1;

        if (kt + 1 < Nk) {
            const int ko = (kt + 1) << 4;
            rAh = *(const uint4*)(gAh + ko);
            rAl = *(const uint4*)(gAl + ko);
            rBh = *(const uint4*)(gBh + ko);
            rBl = *(const uint4*)(gBl + ko);
        }

        const __nv_bfloat16* sAh = smb + cur * 12288;
        const __nv_bfloat16* sAl = sAh + 3072;
        const __nv_bfloat16* sBh = sAh + 6144;
        const __nv_bfloat16* sBl = sAh + 9216;

        wmma::fragment<wmma::matrix_b, 16, 16, 16, __nv_bfloat16,
                       wmma::col_major> fbh[2], fbl[2];
        #pragma unroll
        for (int nt = 0; nt < 2; nt++) {
            const int nl = wn * 32 + nt * 16;
            wmma::load_matrix_sync(fbh[nt], sBh + nl * 24, 24);
            wmma::load_matrix_sync(fbl[nt], sBl + nl * 24, 24);
        }

        #pragma unroll
        for (int mt = 0; mt < 4; mt++) {
            const int ml = wm * 64 + mt * 16;
            wmma::fragment<wmma::matrix_a, 16, 16, 16, __nv_bfloat16,
                           wmma::row_major> fah, fal;
            wmma::load_matrix_sync(fah, sAh + ml * 24, 24);
            wmma::load_matrix_sync(fal, sAl + ml * 24, 24);
            #pragma unroll
            for (int nt = 0; nt < 2; nt++) {
                wmma::mma_sync(acc[mt][nt], fah, fbh[nt], acc[mt][nt]);
                wmma::mma_sync(acc[mt][nt], fah, fbl[nt], acc[mt][nt]);
                wmma::mma_sync(acc[mt][nt], fal, fbh[nt], acc[mt][nt]);
            }
        }

        if (kt + 1 < Nk) {
            *(uint4*)(smb + nxt * 12288 + 0 * 3072 + soff) = rAh;
            *(uint4*)(smb + nxt * 12288 + 1 * 3072 + soff) = rAl;
            *(uint4*)(smb + nxt * 12288 + 2 * 3072 + soff) = rBh;
            *(uint4*)(smb + nxt * 12288 + 3 * 3072 + soff) = rBl;
        }
        __syncthreads();
    }

    /* Epilogue: per 16x16 tile, stage in padded scratch (ldm 20) then
       write out[(t*4H + col)*32 + b] as 2x64B contiguous chunks.      */
    float* myscr = csc + wid * 320;
    const int r  = lane & 15;                  /* b-offset within tile */
    const int ch = lane >> 4;                  /* column half 0/1      */
    #pragma unroll
    for (int mt = 0; mt < 4; mt++) {
        const int m1 = m0 + wm * 64 + mt * 16;
        const int t1 = m1 >> 5;
        const int b1 = (m1 & 31) + r;
        #pragma unroll
        for (int nt = 0; nt < 2; nt++) {
            wmma::store_matrix_sync(myscr, acc[mt][nt], 20, wmma::mem_row_major);
            __syncwarp();
            #pragma unroll
            for (int q = 0; q < 8; q++) {
                const int cc  = ch * 8 + q;
                const int col = col0 + wn * 32 + nt * 16 + cc;
                out[((size_t)t1 * G4 + col) * 32 + b1] =
                    myscr[r * 20 + cc] + __ldg(&bias[col]);
            }
            __syncwarp();
        }
    }
}

/* ------------------------------------------------------------------ */
/* Persistent bidirectional LSTM recurrence (one layer).              */
/* Layer 0 (writeSplit=1): emits bf16 hi/lo [m][2H] for layer-1 GEMM. */
/* Layer 1 (writeSplit=0): emits final f32 output [b][t][2H].         */
/* ------------------------------------------------------------------ */
__global__ void __launch_bounds__(256, 1)
lstm_rec_kernel(const float* __restrict__ xgF, const float* __restrict__ xgB,
                const float* __restrict__ WtF, const float* __restrict__ WtB,
                __nv_bfloat16* __restrict__ oAh, __nv_bfloat16* __restrict__ oAl,
                float* __restrict__ outf, int writeSplit)
{
    extern __shared__ float sm[];
    float* w_s = sm;                       /* 16384 floats = 64 KB       */
    float* h_s = sm + 16384;               /* 32 rows * 516 floats       */

    const int tid = threadIdx.x;
    const int dir = blockIdx.x >> 6;
    const int dd  = blockIdx.x & 63;
    const int wl  = tid >> 5;
    const int b   = tid & 31;
    const int hid = dd * 8 + wl;

    const float* xg = dir ? xgB : xgF;
    const float* Wt = dir ? WtB : WtF;

    for (int i = tid; i < 4096; i += 256) {          /* float4 units    */
        int dwl = i >> 9;
        int gg2 = (i >> 7) & 3;
        int kc  = i & 127;
        float4 v = __ldg((const float4*)Wt +
                         ((size_t)(gg2 * H_ + dd * 8 + dwl) * H_ / 4) + kc);
        *((float4*)w_s + (size_t)dwl * 512 + gg2 * 128 + kc) = v;
    }
    __syncthreads();

    const float4* wg0 = (const float4*)(w_s + wl * 2048);
    const float4* wg1 = wg0 + 128;
    const float4* wg2 = wg0 + 256;
    const float4* wg3 = wg0 + 384;
    const float4* hp  = (const float4*)(h_s + b * 516);

    float c = 0.0f;
    float* hw0 = &g_h[dir][0][b * H_ + hid];
    float* hw1 = &g_h[dir][1][b * H_ + hid];

    for (int s = 0; s < T_; s++) {
        const int t = dir ? (T_ - 1 - s) : s;
        const float* xr = xg + ((size_t)t * G4 + hid) * 32 + b;
        float a0 = xr[0 * H_ * 32];
        float a1 = xr[1 * H_ * 32];
        float a2 = xr[2 * H_ * 32];
        float a3 = xr[3 * H_ * 32];

        if (s > 0) {
            const float4* hsrc = (const float4*)g_h[dir][(s - 1) & 1];
            for (int idx = tid; idx < (B_ * H_ / 4); idx += 256) {
                int bb = idx >> 7;
                int kc = idx & 127;
                float4 v = __ldcg(hsrc + idx);
                *(float4*)&h_s[bb * 516 + kc * 4] = v;
            }
            __syncthreads();

            #pragma unroll 8
            for (int kc = 0; kc < 128; kc++) {
                float4 hv = hp[kc];
                float4 wa = wg0[kc];
                float4 wb = wg1[kc];
                float4 wc = wg2[kc];
                float4 wd = wg3[kc];
                a0 += hv.x * wa.x + hv.y * wa.y + hv.z * wa.z + hv.w * wa.w;
                a1 += hv.x * wb.x + hv.y * wb.y + hv.z * wb.z + hv.w * wb.w;
                a2 += hv.x * wc.x + hv.y * wc.y + hv.z * wc.z + hv.w * wc.w;
                a3 += hv.x * wd.x + hv.y * wd.y + hv.z * wd.z + hv.w * wd.w;
            }
        }

        float ig = sigmoidf_(a0);
        float fg = sigmoidf_(a1);
        float gg = tanhf(a2);
        float og = sigmoidf_(a3);
        c = fg * c + ig * gg;
        float h = og * tanhf(c);

        if (writeSplit) {
            /* layer-1 GEMM operand: [m = t*B+b][k = dir*H + hid] */
            size_t oi = ((size_t)(t * B_ + b)) * (2 * H_) + dir * H_ + hid;
            __nv_bfloat16 hh, hl;
            bf16_split(h, hh, hl);
            oAh[oi] = hh;
            oAl[oi] = hl;
        } else {
            outf[(size_t)(b * T_ + t) * (2 * H_) + dir * H_ + hid] = h;
        }
        __stcg((s & 1) ? hw1 : hw0, h);

        if (s != T_ - 1) grid_barrier();
    }
}

/* ------------------------------------------------------------------ */
/* Host launcher                                                      */
/* ------------------------------------------------------------------ */
extern "C" void kernel_launch(void* const* d_in, const int* in_sizes, int n_in,
                              void* d_out, int out_size)
{
    const float* x     = (const float*)d_in[0];
    const float* wih0f = (const float*)d_in[1];
    const float* whh0f = (const float*)d_in[2];
    const float* b0f   = (const float*)d_in[3];
    const float* wih0b = (const float*)d_in[4];
    const float* whh0b = (const float*)d_in[5];
    const float* b0b   = (const float*)d_in[6];
    const float* wih1f = (const float*)d_in[7];
    const float* whh1f = (const float*)d_in[8];
    const float* b1f   = (const float*)d_in[9];
    const float* wih1b = (const float*)d_in[10];
    const float* whh1b = (const float*)d_in[11];
    const float* b1b   = (const float*)d_in[12];

    float *xgF, *xgB, *wt;
    __nv_bfloat16 *ah0, *al0, *ah1, *al1, *wsp0, *wsp1;
    cudaGetSymbolAddress((void**)&xgF,  g_xgF);
    cudaGetSymbolAddress((void**)&xgB,  g_xgB);
    cudaGetSymbolAddress((void**)&wt,   g_Wt);
    cudaGetSymbolAddress((void**)&ah0,  g_Ah0);
    cudaGetSymbolAddress((void**)&al0,  g_Al0);
    cudaGetSymbolAddress((void**)&ah1,  g_Ah1);
    cudaGetSymbolAddress((void**)&al1,  g_Al1);
    cudaGetSymbolAddress((void**)&wsp0, g_Wsp0);
    cudaGetSymbolAddress((void**)&wsp1, g_Wsp1);

    const size_t WSET  = (size_t)G4 * H_;
    const size_t WS0   = (size_t)G4 * 512;    /* one layer-0 split matrix */
    const size_t WS1   = (size_t)G4 * 1024;
    const int REC_SMEM  = 65536 + 32 * 516 * 4;   /* 131584 B */
    const int GEMM_SMEM = 49152 + 8 * 320 * 4;    /* 59392 B  */
    cudaFuncSetAttribute(lstm_rec_kernel,
                         cudaFuncAttributeMaxDynamicSharedMemorySize, REC_SMEM);
    cudaFuncSetAttribute(gemm_wmma_kernel,
                         cudaFuncAttributeMaxDynamicSharedMemorySize, GEMM_SMEM);

    /* operand prep */
    split_x_kernel<<<16384, 256>>>(x, ah0, al0);

    dim3 tb(32, 8);
    transpose_split_w<<<dim3(64, 16), tb>>>(wih0f, wsp0 + 0 * WS0, wsp0 + 1 * WS0, 512);
    transpose_split_w<<<dim3(64, 16), tb>>>(wih0b, wsp0 + 2 * WS0, wsp0 + 3 * WS0, 512);
    transpose_split_w<<<dim3(64, 32), tb>>>(wih1f, wsp1 + 0 * WS1, wsp1 + 1 * WS1, 1024);
    transpose_split_w<<<dim3(64, 32), tb>>>(wih1b, wsp1 + 2 * WS1, wsp1 + 3 * WS1, 1024);

    dim3 tg(G4 / 32, H_ / 32);
    transpose_whh<<<tg, tb>>>(whh0f, wt + 0 * WSET);
    transpose_whh<<<tg, tb>>>(whh0b, wt + 1 * WSET);
    transpose_whh<<<tg, tb>>>(whh1f, wt + 2 * WSET);
    transpose_whh<<<tg, tb>>>(whh1b, wt + 3 * WSET);

    dim3 gg(G4 / 128, 8192 / 128);             /* (16, 64) */

    /* layer 0 input GEMMs (tensor cores via WMMA) */
    gemm_wmma_kernel<<<gg, 256, GEMM_SMEM>>>(ah0, al0,
        wsp0 + 0 * WS0, wsp0 + 1 * WS0, b0f, xgF, 512);
    gemm_wmma_kernel<<<gg, 256, GEMM_SMEM>>>(ah0, al0,
        wsp0 + 2 * WS0, wsp0 + 3 * WS0, b0b, xgB, 512);
    /* layer 0 recurrence -> bf16 split operand for layer 1 */
    lstm_rec_kernel<<<NREC_CTAS, 256, REC_SMEM>>>(
        xgF, xgB, wt + 0 * WSET, wt + 1 * WSET, ah1, al1, nullptr, 1);
    /* layer 1 input GEMMs */
    gemm_wmma_kernel<<<gg, 256, GEMM_SMEM>>>(ah1, al1,
        wsp1 + 0 * WS1, wsp1 + 1 * WS1, b1f, xgF, 1024);
    gemm_wmma_kernel<<<gg, 256, GEMM_SMEM>>>(ah1, al1,
        wsp1 + 2 * WS1, wsp1 + 3 * WS1, b1b, xgB, 1024);
    /* layer 1 recurrence -> final output */
    lstm_rec_kernel<<<NREC_CTAS, 256, REC_SMEM>>>(
        xgF, xgB, wt + 2 * WSET, wt + 3 * WSET, nullptr, nullptr,
        (float*)d_out, 0);
}

// round 9
// speedup vs baseline: 1.6215x; 1.0316x over previous
#include <cuda_runtime.h>
#include <cuda_bf16.h>
#include <mma.h>
#include <math.h>
#include <stdint.h>

using namespace nvcuda;

#define B_   32
#define T_   256
#define IN_  512
#define H_   512
#define G4   2048   /* 4*H */
#define NREC_CTAS 128

/* ------------------------------------------------------------------ */
/* Static device scratch                                              */
/* ------------------------------------------------------------------ */
__device__ float g_xgF[(size_t)T_ * B_ * G4];          /* 64 MB, [t][col][b] */
__device__ float g_xgB[(size_t)T_ * B_ * G4];          /* 64 MB, [t][col][b] */
__device__ float g_Wt[4][(size_t)G4 * H_];             /* W_hh transposed [4H][H] */
__device__ float g_h[2][2][B_ * H_];                   /* [dir][parity][b*H+h] */
__device__ unsigned g_barCount[2][32];                 /* per-dir, line-padded */
__device__ unsigned g_barGen[2][32];

/* bf16 hi/lo split operands for the tensor-core input GEMMs */
__device__ __nv_bfloat16 g_Ah0[(size_t)8192 * 512];    /* layer0 A hi [m][k] */
__device__ __nv_bfloat16 g_Al0[(size_t)8192 * 512];
__device__ __nv_bfloat16 g_Ah1[(size_t)8192 * 1024];   /* layer1 A hi [m][k] */
__device__ __nv_bfloat16 g_Al1[(size_t)8192 * 1024];
__device__ __nv_bfloat16 g_Wsp0[2][2][(size_t)G4 * 512];   /* [dir][hi/lo][n][k] */
__device__ __nv_bfloat16 g_Wsp1[2][2][(size_t)G4 * 1024];

/* ------------------------------------------------------------------ */
/* Per-direction grid barrier (64 CTAs each, co-resident)             */
/* ------------------------------------------------------------------ */
__device__ __forceinline__ void grid_barrier_dir(int dir)
{
    __threadfence();
    __syncthreads();
    if (threadIdx.x == 0) {
        unsigned gen = *((volatile unsigned*)&g_barGen[dir][0]);
        unsigned arrived = atomicAdd(&g_barCount[dir][0], 1u);
        if (arrived == (NREC_CTAS / 2) - 1) {
            atomicExch(&g_barCount[dir][0], 0u);
            __threadfence();
            atomicAdd(&g_barGen[dir][0], 1u);
        } else {
            while (*((volatile unsigned*)&g_barGen[dir][0]) == gen) {
                __nanosleep(32);
            }
        }
    }
    __syncthreads();
    __threadfence();
}

__device__ __forceinline__ float sigmoidf_(float x)
{
    return 1.0f / (1.0f + expf(-x));
}

__device__ __forceinline__ void bf16_split(float v, __nv_bfloat16& h, __nv_bfloat16& l)
{
    h = __float2bfloat16(v);
    l = __float2bfloat16(v - __bfloat162float(h));
}

/* ------------------------------------------------------------------ */
/* x [B][T][IN] fp32 -> Ah/Al [m=t*B+b][k] bf16 hi/lo                 */
/* ------------------------------------------------------------------ */
__global__ void split_x_kernel(const float* __restrict__ x,
                               __nv_bfloat16* __restrict__ Ah,
                               __nv_bfloat16* __restrict__ Al)
{
    int idx = blockIdx.x * blockDim.x + threadIdx.x;   /* < 8192*512 */
    int m = idx >> 9;
    int k = idx & 511;
    int b = m & 31;
    int t = m >> 5;
    float v = x[((size_t)b * T_ + t) * IN_ + k];
    __nv_bfloat16 h, l;
    bf16_split(v, h, l);
    Ah[idx] = h;
    Al[idx] = l;
}

/* ------------------------------------------------------------------ */
/* W_ih [Din][4H] fp32 -> Wh/Wl [4H][Din] bf16 hi/lo (transposed)     */
/* ------------------------------------------------------------------ */
__global__ void transpose_split_w(const float* __restrict__ W,
                                  __nv_bfloat16* __restrict__ Wh,
                                  __nv_bfloat16* __restrict__ Wl, int Din)
{
    __shared__ float tile[32][33];
    int x  = blockIdx.x * 32 + threadIdx.x;   /* col n in W */
    int y0 = blockIdx.y * 32;                 /* k base     */
    #pragma unroll
    for (int i = threadIdx.y; i < 32; i += 8)
        tile[i][threadIdx.x] = W[(size_t)(y0 + i) * G4 + x];
    __syncthreads();
    int k  = y0 + threadIdx.x;
    int n0 = blockIdx.x * 32;
    #pragma unroll
    for (int i = threadIdx.y; i < 32; i += 8) {
        float v = tile[threadIdx.x][i];
        __nv_bfloat16 h, l;
        bf16_split(v, h, l);
        Wh[(size_t)(n0 + i) * Din + k] = h;
        Wl[(size_t)(n0 + i) * Din + k] = l;
    }
}

/* ------------------------------------------------------------------ */
/* Transpose all 4 W_hh [H,4H] -> Wt [4H,H], fused via blockIdx.z     */
/* ------------------------------------------------------------------ */
__global__ void transpose_whh4(const float* __restrict__ w0,
                               const float* __restrict__ w1,
                               const float* __restrict__ w2,
                               const float* __restrict__ w3,
                               float* __restrict__ wtbase)
{
    const float* W = (blockIdx.z == 0) ? w0 : (blockIdx.z == 1) ? w1 :
                     (blockIdx.z == 2) ? w2 : w3;
    float* Wt = wtbase + (size_t)blockIdx.z * G4 * H_;
    __shared__ float tile[32][33];
    int x  = blockIdx.x * 32 + threadIdx.x;
    int y0 = blockIdx.y * 32;
    #pragma unroll
    for (int i = threadIdx.y; i < 32; i += 8)
        tile[i][threadIdx.x] = W[(size_t)(y0 + i) * G4 + x];
    __syncthreads();
    int k  = y0 + threadIdx.x;
    int c0 = blockIdx.x * 32;
    #pragma unroll
    for (int i = threadIdx.y; i < 32; i += 8)
        Wt[(size_t)(c0 + i) * H_ + k] = tile[threadIdx.x][i];
}

/* ------------------------------------------------------------------ */
/* WMMA input GEMM, split-bf16 (3 products), fp32 accumulate.         */
/* ------------------------------------------------------------------ */
__global__ void __launch_bounds__(256)
gemm_wmma_kernel(const __nv_bfloat16* __restrict__ Ah,
                 const __nv_bfloat16* __restrict__ Al,
                 const __nv_bfloat16* __restrict__ Bh,
                 const __nv_bfloat16* __restrict__ Bl,
                 const float* __restrict__ bias,
                 float* __restrict__ out, int Din)
{
    extern __shared__ char smraw[];
    __nv_bfloat16* smb = (__nv_bfloat16*)smraw;     /* 2 bufs x 4 mats x 3072 elem */
    float* csc = (float*)(smraw + 49152);           /* 8 warps x 320 floats        */

    const int tid  = threadIdx.x;
    const int lane = tid & 31;
    const int wid  = tid >> 5;
    const int wm   = wid >> 2;                 /* 0..1 */
    const int wn   = wid & 3;                  /* 0..3 */
    const int m0   = blockIdx.y * 128;
    const int col0 = blockIdx.x * 128;

    const int lr = tid >> 1;
    const int lh = tid & 1;
    const __nv_bfloat16* gAh = Ah + (size_t)(m0 + lr) * Din + lh * 8;
    const __nv_bfloat16* gAl = Al + (size_t)(m0 + lr) * Din + lh * 8;
    const __nv_bfloat16* gBh = Bh + (size_t)(col0 + lr) * Din + lh * 8;
    const __nv_bfloat16* gBl = Bl + (size_t)(col0 + lr) * Din + lh * 8;
    const int soff = lr * 24 + lh * 8;

    wmma::fragment<wmma::accumulator, 16, 16, 16, float> acc[4][2];
    #pragma unroll
    for (int i = 0; i < 4; i++)
        #pragma unroll
        for (int j = 0; j < 2; j++)
            wmma::fill_fragment(acc[i][j], 0.0f);

    uint4 rAh = *(const uint4*)gAh;
    uint4 rAl = *(const uint4*)gAl;
    uint4 rBh = *(const uint4*)gBh;
    uint4 rBl = *(const uint4*)gBl;

    *(uint4*)(smb + 0 * 12288 + 0 * 3072 + soff) = rAh;
    *(uint4*)(smb + 0 * 12288 + 1 * 3072 + soff) = rAl;
    *(uint4*)(smb + 0 * 12288 + 2 * 3072 + soff) = rBh;
    *(uint4*)(smb + 0 * 12288 + 3 * 3072 + soff) = rBl;
    __syncthreads();

    const int Nk = Din >> 4;
    for (int kt = 0; kt < Nk; kt++) {
        const int cur = kt & 1;
        const int nxt = cur ^ 1;

        if (kt + 1 < Nk) {
            const int ko = (kt + 1) << 4;
            rAh = *(const uint4*)(gAh + ko);
            rAl = *(const uint4*)(gAl + ko);
            rBh = *(const uint4*)(gBh + ko);
            rBl = *(const uint4*)(gBl + ko);
        }

        const __nv_bfloat16* sAh = smb + cur * 12288;
        const __nv_bfloat16* sAl = sAh + 3072;
        const __nv_bfloat16* sBh = sAh + 6144;
        const __nv_bfloat16* sBl = sAh + 9216;

        wmma::fragment<wmma::matrix_b, 16, 16, 16, __nv_bfloat16,
                       wmma::col_major> fbh[2], fbl[2];
        #pragma unroll
        for (int nt = 0; nt < 2; nt++) {
            const int nl = wn * 32 + nt * 16;
            wmma::load_matrix_sync(fbh[nt], sBh + nl * 24, 24);
            wmma::load_matrix_sync(fbl[nt], sBl + nl * 24, 24);
        }

        #pragma unroll
        for (int mt = 0; mt < 4; mt++) {
            const int ml = wm * 64 + mt * 16;
            wmma::fragment<wmma::matrix_a, 16, 16, 16, __nv_bfloat16,
                           wmma::row_major> fah, fal;
            wmma::load_matrix_sync(fah, sAh + ml * 24, 24);
            wmma::load_matrix_sync(fal, sAl + ml * 24, 24);
            #pragma unroll
            for (int nt = 0; nt < 2; nt++) {
                wmma::mma_sync(acc[mt][nt], fah, fbh[nt], acc[mt][nt]);
                wmma::mma_sync(acc[mt][nt], fah, fbl[nt], acc[mt][nt]);
                wmma::mma_sync(acc[mt][nt], fal, fbh[nt], acc[mt][nt]);
            }
        }

        if (kt + 1 < Nk) {
            *(uint4*)(smb + nxt * 12288 + 0 * 3072 + soff) = rAh;
            *(uint4*)(smb + nxt * 12288 + 1 * 3072 + soff) = rAl;
            *(uint4*)(smb + nxt * 12288 + 2 * 3072 + soff) = rBh;
            *(uint4*)(smb + nxt * 12288 + 3 * 3072 + soff) = rBl;
        }
        __syncthreads();
    }

    /* Epilogue via padded scratch -> out[(t*4H + col)*32 + b] + bias  */
    float* myscr = csc + wid * 320;
    const int r  = lane & 15;
    const int ch = lane >> 4;
    #pragma unroll
    for (int mt = 0; mt < 4; mt++) {
        const int m1 = m0 + wm * 64 + mt * 16;
        const int t1 = m1 >> 5;
        const int b1 = (m1 & 31) + r;
        #pragma unroll
        for (int nt = 0; nt < 2; nt++) {
            wmma::store_matrix_sync(myscr, acc[mt][nt], 20, wmma::mem_row_major);
            __syncwarp();
            #pragma unroll
            for (int q = 0; q < 8; q++) {
                const int cc  = ch * 8 + q;
                const int col = col0 + wn * 32 + nt * 16 + cc;
                out[((size_t)t1 * G4 + col) * 32 + b1] =
                    myscr[r * 20 + cc] + __ldg(&bias[col]);
            }
            __syncwarp();
        }
    }
}

/* ------------------------------------------------------------------ */
/* Persistent bidirectional LSTM recurrence (one layer).              */
/* xg prefetched across the barrier; per-dir barrier.                 */
/* ------------------------------------------------------------------ */
__global__ void __launch_bounds__(256, 1)
lstm_rec_kernel(const float* __restrict__ xgF, const float* __restrict__ xgB,
                const float* __restrict__ WtF, const float* __restrict__ WtB,
                __nv_bfloat16* __restrict__ oAh, __nv_bfloat16* __restrict__ oAl,
                float* __restrict__ outf, int writeSplit)
{
    extern __shared__ float sm[];
    float* w_s = sm;                       /* 16384 floats = 64 KB       */
    float* h_s = sm + 16384;               /* 32 rows * 516 floats       */

    const int tid = threadIdx.x;
    const int dir = blockIdx.x >> 6;
    const int dd  = blockIdx.x & 63;
    const int wl  = tid >> 5;
    const int b   = tid & 31;
    const int hid = dd * 8 + wl;

    const float* xg = dir ? xgB : xgF;
    const float* Wt = dir ? WtB : WtF;

    for (int i = tid; i < 4096; i += 256) {          /* float4 units    */
        int dwl = i >> 9;
        int gg2 = (i >> 7) & 3;
        int kc  = i & 127;
        float4 v = __ldg((const float4*)Wt +
                         ((size_t)(gg2 * H_ + dd * 8 + dwl) * H_ / 4) + kc);
        *((float4*)w_s + (size_t)dwl * 512 + gg2 * 128 + kc) = v;
    }
    __syncthreads();

    const float4* wg0 = (const float4*)(w_s + wl * 2048);
    const float4* wg1 = wg0 + 128;
    const float4* wg2 = wg0 + 256;
    const float4* wg3 = wg0 + 384;
    const float4* hp  = (const float4*)(h_s + b * 516);

    float c = 0.0f;
    float* hw0 = &g_h[dir][0][b * H_ + hid];
    float* hw1 = &g_h[dir][1][b * H_ + hid];

    /* prefetch xg for step 0 */
    const int t_first = dir ? (T_ - 1) : 0;
    const float* xr0 = xg + ((size_t)t_first * G4 + hid) * 32 + b;
    float p0 = xr0[0 * H_ * 32];
    float p1 = xr0[1 * H_ * 32];
    float p2 = xr0[2 * H_ * 32];
    float p3 = xr0[3 * H_ * 32];

    for (int s = 0; s < T_; s++) {
        const int t = dir ? (T_ - 1 - s) : s;
        float a0 = p0, a1 = p1, a2 = p2, a3 = p3;

        if (s > 0) {
            const float4* hsrc = (const float4*)g_h[dir][(s - 1) & 1];
            for (int idx = tid; idx < (B_ * H_ / 4); idx += 256) {
                int bb = idx >> 7;
                int kc = idx & 127;
                float4 v = __ldcg(hsrc + idx);
                *(float4*)&h_s[bb * 516 + kc * 4] = v;
            }
            __syncthreads();

            #pragma unroll 8
            for (int kc = 0; kc < 128; kc++) {
                float4 hv = hp[kc];
                float4 wa = wg0[kc];
                float4 wb = wg1[kc];
                float4 wc = wg2[kc];
                float4 wd = wg3[kc];
                a0 += hv.x * wa.x + hv.y * wa.y + hv.z * wa.z + hv.w * wa.w;
                a1 += hv.x * wb.x + hv.y * wb.y + hv.z * wb.z + hv.w * wb.w;
                a2 += hv.x * wc.x + hv.y * wc.y + hv.z * wc.z + hv.w * wc.w;
                a3 += hv.x * wd.x + hv.y * wd.y + hv.z * wd.z + hv.w * wd.w;
            }
        }

        float ig = sigmoidf_(a0);
        float fg = sigmoidf_(a1);
        float gg = tanhf(a2);
        float og = sigmoidf_(a3);
        c = fg * c + ig * gg;
        float h = og * tanhf(c);

        if (writeSplit) {
            size_t oi = ((size_t)(t * B_ + b)) * (2 * H_) + dir * H_ + hid;
            __nv_bfloat16 hh, hl;
            bf16_split(h, hh, hl);
            oAh[oi] = hh;
            oAl[oi] = hl;
        } else {
            outf[(size_t)(b * T_ + t) * (2 * H_) + dir * H_ + hid] = h;
        }
        __stcg((s & 1) ? hw1 : hw0, h);

        if (s != T_ - 1) {
            /* prefetch next step's xg BEFORE the barrier: DRAM latency
               hides under the barrier wait. */
            const int tn = dir ? (T_ - 2 - s) : (s + 1);
            const float* xr = xg + ((size_t)tn * G4 + hid) * 32 + b;
            p0 = xr[0 * H_ * 32];
            p1 = xr[1 * H_ * 32];
            p2 = xr[2 * H_ * 32];
            p3 = xr[3 * H_ * 32];
            grid_barrier_dir(dir);
        }
    }
}

/* ------------------------------------------------------------------ */
/* Host launcher                                                      */
/* ------------------------------------------------------------------ */
extern "C" void kernel_launch(void* const* d_in, const int* in_sizes, int n_in,
                              void* d_out, int out_size)
{
    const float* x     = (const float*)d_in[0];
    const float* wih0f = (const float*)d_in[1];
    const float* whh0f = (const float*)d_in[2];
    const float* b0f   = (const float*)d_in[3];
    const float* wih0b = (const float*)d_in[4];
    const float* whh0b = (const float*)d_in[5];
    const float* b0b   = (const float*)d_in[6];
    const float* wih1f = (const float*)d_in[7];
    const float* whh1f = (const float*)d_in[8];
    const float* b1f   = (const float*)d_in[9];
    const float* wih1b = (const float*)d_in[10];
    const float* whh1b = (const float*)d_in[11];
    const float* b1b   = (const float*)d_in[12];

    float *xgF, *xgB, *wt;
    __nv_bfloat16 *ah0, *al0, *ah1, *al1, *wsp0, *wsp1;
    cudaGetSymbolAddress((void**)&xgF,  g_xgF);
    cudaGetSymbolAddress((void**)&xgB,  g_xgB);
    cudaGetSymbolAddress((void**)&wt,   g_Wt);
    cudaGetSymbolAddress((void**)&ah0,  g_Ah0);
    cudaGetSymbolAddress((void**)&al0,  g_Al0);
    cudaGetSymbolAddress((void**)&ah1,  g_Ah1);
    cudaGetSymbolAddress((void**)&al1,  g_Al1);
    cudaGetSymbolAddress((void**)&wsp0, g_Wsp0);
    cudaGetSymbolAddress((void**)&wsp1, g_Wsp1);

    const size_t WSET  = (size_t)G4 * H_;
    const size_t WS0   = (size_t)G4 * 512;
    const size_t WS1   = (size_t)G4 * 1024;
    const int REC_SMEM  = 65536 + 32 * 516 * 4;   /* 131584 B */
    const int GEMM_SMEM = 49152 + 8 * 320 * 4;    /* 59392 B  */
    cudaFuncSetAttribute(lstm_rec_kernel,
                         cudaFuncAttributeMaxDynamicSharedMemorySize, REC_SMEM);
    cudaFuncSetAttribute(gemm_wmma_kernel,
                         cudaFuncAttributeMaxDynamicSharedMemorySize, GEMM_SMEM);

    dim3 tb(32, 8);
    dim3 gg(G4 / 128, 8192 / 128);             /* (16, 64) */

    /* launch order arranged so ncu (-s 5) profiles a GEMM             */
    transpose_whh4<<<dim3(64, 16, 4), tb>>>(whh0f, whh0b, whh1f, whh1b, wt); /*0*/
    split_x_kernel<<<16384, 256>>>(x, ah0, al0);                             /*1*/
    transpose_split_w<<<dim3(64, 16), tb>>>(wih0f, wsp0 + 0 * WS0,
                                            wsp0 + 1 * WS0, 512);            /*2*/
    transpose_split_w<<<dim3(64, 16), tb>>>(wih0b, wsp0 + 2 * WS0,
                                            wsp0 + 3 * WS0, 512);            /*3*/
    gemm_wmma_kernel<<<gg, 256, GEMM_SMEM>>>(ah0, al0,
        wsp0 + 0 * WS0, wsp0 + 1 * WS0, b0f, xgF, 512);                      /*4*/
    gemm_wmma_kernel<<<gg, 256, GEMM_SMEM>>>(ah0, al0,
        wsp0 + 2 * WS0, wsp0 + 3 * WS0, b0b, xgB, 512);                      /*5*/
    lstm_rec_kernel<<<NREC_CTAS, 256, REC_SMEM>>>(
        xgF, xgB, wt + 0 * WSET, wt + 1 * WSET, ah1, al1, nullptr, 1);       /*6*/
    transpose_split_w<<<dim3(64, 32), tb>>>(wih1f, wsp1 + 0 * WS1,
                                            wsp1 + 1 * WS1, 1024);           /*7*/
    transpose_split_w<<<dim3(64, 32), tb>>>(wih1b, wsp1 + 2 * WS1,
                                            wsp1 + 3 * WS1, 1024);           /*8*/
    gemm_wmma_kernel<<<gg, 256, GEMM_SMEM>>>(ah1, al1,
        wsp1 + 0 * WS1, wsp1 + 1 * WS1, b1f, xgF, 1024);                     /*9*/
    gemm_wmma_kernel<<<gg, 256, GEMM_SMEM>>>(ah1, al1,
        wsp1 + 2 * WS1, wsp1 + 3 * WS1, b1b, xgB, 1024);                     /*10*/
    lstm_rec_kernel<<<NREC_CTAS, 256, REC_SMEM>>>(
        xgF, xgB, wt + 2 * WSET, wt + 3 * WSET, nullptr, nullptr,
        (float*)d_out, 0);                                                   /*11*/
}

// round 10
// speedup vs baseline: 2.3756x; 1.4651x over previous
#include <cuda_runtime.h>
#include <cuda_bf16.h>
#include <mma.h>
#include <math.h>
#include <stdint.h>

using namespace nvcuda;

#define B_   32
#define T_   256
#define IN_  512
#define H_   512
#define G4   2048   /* 4*H */
#define NREC_CTAS 128

/* ------------------------------------------------------------------ */
/* Static device scratch                                              */
/* ------------------------------------------------------------------ */
__device__ float g_xgF[(size_t)T_ * B_ * G4];          /* 64 MB, [t][col][b] */
__device__ float g_xgB[(size_t)T_ * B_ * G4];          /* 64 MB, [t][col][b] */
__device__ unsigned g_barCount[2][32];
__device__ unsigned g_barGen[2][32];

/* recurrent h state, bf16 hi/lo, layout [k=hid][b], double-buffered  */
__device__ __nv_bfloat16 g_hbfH[2][2][H_ * B_];
__device__ __nv_bfloat16 g_hbfL[2][2][H_ * B_];

/* bf16 hi/lo split operands for the tensor-core input GEMMs */
__device__ __nv_bfloat16 g_Ah0[(size_t)8192 * 512];
__device__ __nv_bfloat16 g_Al0[(size_t)8192 * 512];
__device__ __nv_bfloat16 g_Ah1[(size_t)8192 * 1024];
__device__ __nv_bfloat16 g_Al1[(size_t)8192 * 1024];
__device__ __nv_bfloat16 g_Wsp0[2][2][(size_t)G4 * 512];
__device__ __nv_bfloat16 g_Wsp1[2][2][(size_t)G4 * 1024];

/* packed recurrent weights: [layer*2+dir][hi/lo][col'=dd*32+g*8+j][k] */
__device__ __nv_bfloat16 g_WpkH[4][(size_t)G4 * H_];
__device__ __nv_bfloat16 g_WpkL[4][(size_t)G4 * H_];

/* ------------------------------------------------------------------ */
__device__ __forceinline__ void grid_barrier_dir(int dir)
{
    __threadfence();
    __syncthreads();
    if (threadIdx.x == 0) {
        unsigned gen = *((volatile unsigned*)&g_barGen[dir][0]);
        unsigned arrived = atomicAdd(&g_barCount[dir][0], 1u);
        if (arrived == (NREC_CTAS / 2) - 1) {
            atomicExch(&g_barCount[dir][0], 0u);
            __threadfence();
            atomicAdd(&g_barGen[dir][0], 1u);
        } else {
            while (*((volatile unsigned*)&g_barGen[dir][0]) == gen) {
                __nanosleep(32);
            }
        }
    }
    __syncthreads();
    __threadfence();
}

__device__ __forceinline__ float sigmoidf_(float x)
{
    return 1.0f / (1.0f + expf(-x));
}

__device__ __forceinline__ void bf16_split(float v, __nv_bfloat16& h, __nv_bfloat16& l)
{
    h = __float2bfloat16(v);
    l = __float2bfloat16(v - __bfloat162float(h));
}

/* ------------------------------------------------------------------ */
/* x [B][T][IN] fp32 -> Ah/Al [m=t*B+b][k] bf16 hi/lo                 */
/* ------------------------------------------------------------------ */
__global__ void split_x_kernel(const float* __restrict__ x,
                               __nv_bfloat16* __restrict__ Ah,
                               __nv_bfloat16* __restrict__ Al)
{
    int idx = blockIdx.x * blockDim.x + threadIdx.x;
    int m = idx >> 9;
    int k = idx & 511;
    int b = m & 31;
    int t = m >> 5;
    float v = x[((size_t)b * T_ + t) * IN_ + k];
    __nv_bfloat16 h, l;
    bf16_split(v, h, l);
    Ah[idx] = h;
    Al[idx] = l;
}

/* ------------------------------------------------------------------ */
/* W_ih [Din][4H] fp32 -> Wh/Wl [4H][Din] bf16 hi/lo (transposed)     */
/* ------------------------------------------------------------------ */
__global__ void transpose_split_w(const float* __restrict__ W,
                                  __nv_bfloat16* __restrict__ Wh,
                                  __nv_bfloat16* __restrict__ Wl, int Din)
{
    __shared__ float tile[32][33];
    int x  = blockIdx.x * 32 + threadIdx.x;
    int y0 = blockIdx.y * 32;
    #pragma unroll
    for (int i = threadIdx.y; i < 32; i += 8)
        tile[i][threadIdx.x] = W[(size_t)(y0 + i) * G4 + x];
    __syncthreads();
    int k  = y0 + threadIdx.x;
    int n0 = blockIdx.x * 32;
    #pragma unroll
    for (int i = threadIdx.y; i < 32; i += 8) {
        float v = tile[threadIdx.x][i];
        __nv_bfloat16 h, l;
        bf16_split(v, h, l);
        Wh[(size_t)(n0 + i) * Din + k] = h;
        Wl[(size_t)(n0 + i) * Din + k] = l;
    }
}

/* ------------------------------------------------------------------ */
/* Pack all 4 W_hh [H,4H] -> bf16 hi/lo [col'][k], col'=dd*32+g*8+j   */
/* (source col c = g*512 + dd*8 + j), fused via blockIdx.z.           */
/* ------------------------------------------------------------------ */
__global__ void pack_whh4(const float* __restrict__ w0,
                          const float* __restrict__ w1,
                          const float* __restrict__ w2,
                          const float* __restrict__ w3)
{
    const int z = blockIdx.z;
    const float* W = (z == 0) ? w0 : (z == 1) ? w1 : (z == 2) ? w2 : w3;
    __nv_bfloat16* Wh = g_WpkH[z];
    __nv_bfloat16* Wl = g_WpkL[z];

    __shared__ float tile[32][33];
    const int tx = threadIdx.x;
    const int k0 = blockIdx.y * 32;
    const int cp0 = blockIdx.x * 32;          /* col' base, dd = blockIdx.x */
    /* source col for col' = cp0 + tx */
    const int c = ((tx >> 3) & 3) * 512 + blockIdx.x * 8 + (tx & 7);
    #pragma unroll
    for (int i = threadIdx.y; i < 32; i += 8)
        tile[i][tx] = W[(size_t)(k0 + i) * G4 + c];
    __syncthreads();
    #pragma unroll
    for (int i = threadIdx.y; i < 32; i += 8) {
        float v = tile[tx][i];                /* W[k0+tx][c(cp0+i)] */
        __nv_bfloat16 h, l;
        bf16_split(v, h, l);
        Wh[(size_t)(cp0 + i) * H_ + k0 + tx] = h;
        Wl[(size_t)(cp0 + i) * H_ + k0 + tx] = l;
    }
}

/* ------------------------------------------------------------------ */
/* WMMA input GEMM, split-bf16 (3 products), fp32 accumulate.         */
/* ------------------------------------------------------------------ */
__global__ void __launch_bounds__(256)
gemm_wmma_kernel(const __nv_bfloat16* __restrict__ Ah,
                 const __nv_bfloat16* __restrict__ Al,
                 const __nv_bfloat16* __restrict__ Bh,
                 const __nv_bfloat16* __restrict__ Bl,
                 const float* __restrict__ bias,
                 float* __restrict__ out, int Din)
{
    extern __shared__ char smraw[];
    __nv_bfloat16* smb = (__nv_bfloat16*)smraw;
    float* csc = (float*)(smraw + 49152);

    const int tid  = threadIdx.x;
    const int lane = tid & 31;
    const int wid  = tid >> 5;
    const int wm   = wid >> 2;
    const int wn   = wid & 3;
    const int m0   = blockIdx.y * 128;
    const int col0 = blockIdx.x * 128;

    const int lr = tid >> 1;
    const int lh = tid & 1;
    const __nv_bfloat16* gAh = Ah + (size_t)(m0 + lr) * Din + lh * 8;
    const __nv_bfloat16* gAl = Al + (size_t)(m0 + lr) * Din + lh * 8;
    const __nv_bfloat16* gBh = Bh + (size_t)(col0 + lr) * Din + lh * 8;
    const __nv_bfloat16* gBl = Bl + (size_t)(col0 + lr) * Din + lh * 8;
    const int soff = lr * 24 + lh * 8;

    wmma::fragment<wmma::accumulator, 16, 16, 16, float> acc[4][2];
    #pragma unroll
    for (int i = 0; i < 4; i++)
        #pragma unroll
        for (int j = 0; j < 2; j++)
            wmma::fill_fragment(acc[i][j], 0.0f);

    uint4 rAh = *(const uint4*)gAh;
    uint4 rAl = *(const uint4*)gAl;
    uint4 rBh = *(const uint4*)gBh;
    uint4 rBl = *(const uint4*)gBl;

    *(uint4*)(smb + 0 * 12288 + 0 * 3072 + soff) = rAh;
    *(uint4*)(smb + 0 * 12288 + 1 * 3072 + soff) = rAl;
    *(uint4*)(smb + 0 * 12288 + 2 * 3072 + soff) = rBh;
    *(uint4*)(smb + 0 * 12288 + 3 * 3072 + soff) = rBl;
    __syncthreads();

    const int Nk = Din >> 4;
    for (int kt = 0; kt < Nk; kt++) {
        const int cur = kt & 1;
        const int nxt = cur ^ 1;

        if (kt + 1 < Nk) {
            const int ko = (kt + 1) << 4;
            rAh = *(const uint4*)(gAh + ko);
            rAl = *(const uint4*)(gAl + ko);
            rBh = *(const uint4*)(gBh + ko);
            rBl = *(const uint4*)(gBl + ko);
        }

        const __nv_bfloat16* sAh = smb + cur * 12288;
        const __nv_bfloat16* sAl = sAh + 3072;
        const __nv_bfloat16* sBh = sAh + 6144;
        const __nv_bfloat16* sBl = sAh + 9216;

        wmma::fragment<wmma::matrix_b, 16, 16, 16, __nv_bfloat16,
                       wmma::col_major> fbh[2], fbl[2];
        #pragma unroll
        for (int nt = 0; nt < 2; nt++) {
            const int nl = wn * 32 + nt * 16;
            wmma::load_matrix_sync(fbh[nt], sBh + nl * 24, 24);
            wmma::load_matrix_sync(fbl[nt], sBl + nl * 24, 24);
        }

        #pragma unroll
        for (int mt = 0; mt < 4; mt++) {
            const int ml = wm * 64 + mt * 16;
            wmma::fragment<wmma::matrix_a, 16, 16, 16, __nv_bfloat16,
                           wmma::row_major> fah, fal;
            wmma::load_matrix_sync(fah, sAh + ml * 24, 24);
            wmma::load_matrix_sync(fal, sAl + ml * 24, 24);
            #pragma unroll
            for (int nt = 0; nt < 2; nt++) {
                wmma::mma_sync(acc[mt][nt], fah, fbh[nt], acc[mt][nt]);
                wmma::mma_sync(acc[mt][nt], fah, fbl[nt], acc[mt][nt]);
                wmma::mma_sync(acc[mt][nt], fal, fbh[nt], acc[mt][nt]);
            }
        }

        if (kt + 1 < Nk) {
            *(uint4*)(smb + nxt * 12288 + 0 * 3072 + soff) = rAh;
            *(uint4*)(smb + nxt * 12288 + 1 * 3072 + soff) = rAl;
            *(uint4*)(smb + nxt * 12288 + 2 * 3072 + soff) = rBh;
            *(uint4*)(smb + nxt * 12288 + 3 * 3072 + soff) = rBl;
        }
        __syncthreads();
    }

    float* myscr = csc + wid * 320;
    const int r  = lane & 15;
    const int ch = lane >> 4;
    #pragma unroll
    for (int mt = 0; mt < 4; mt++) {
        const int m1 = m0 + wm * 64 + mt * 16;
        const int t1 = m1 >> 5;
        const int b1 = (m1 & 31) + r;
        #pragma unroll
        for (int nt = 0; nt < 2; nt++) {
            wmma::store_matrix_sync(myscr, acc[mt][nt], 20, wmma::mem_row_major);
            __syncwarp();
            #pragma unroll
            for (int q = 0; q < 8; q++) {
                const int cc  = ch * 8 + q;
                const int col = col0 + wn * 32 + nt * 16 + cc;
                out[((size_t)t1 * G4 + col) * 32 + b1] =
                    myscr[r * 20 + cc] + __ldg(&bias[col]);
            }
            __syncwarp();
        }
    }
}

/* ------------------------------------------------------------------ */
/* WMMA persistent bidirectional LSTM recurrence (one layer).         */
/* Per dir 64 CTAs; CTA dd owns hids dd*8..dd*8+7 -> 32 gate cols.    */
/* h state global bf16 hi/lo [k=hid][b]; staged to SMEM col_major A.  */
/* Weights (split bf16, col_major B) resident in SMEM.                */
/* Warp w: tile pair p=w>>1 (mt=p>>1,nt=p&1), k-half q=w&1.           */
/* Thread (b=lane, j=warp) owns c in register, applies gates in fp32. */
/* ------------------------------------------------------------------ */
#define LDA 40
#define LDB 520
#define OFF_BWH 0
#define OFF_BWL 33280
#define OFF_HAH 66560
#define OFF_HAL 107520
#define OFF_SCR 148480
#define REC_SMEM 158720

__global__ void __launch_bounds__(256, 1)
lstm_rec_wmma(const float* __restrict__ xgF, const float* __restrict__ xgB,
              const __nv_bfloat16* __restrict__ WFh, const __nv_bfloat16* __restrict__ WFl,
              const __nv_bfloat16* __restrict__ WBh, const __nv_bfloat16* __restrict__ WBl,
              __nv_bfloat16* __restrict__ oAh, __nv_bfloat16* __restrict__ oAl,
              float* __restrict__ outf, int writeSplit)
{
    extern __shared__ char smraw[];
    __nv_bfloat16* bWh = (__nv_bfloat16*)(smraw + OFF_BWH);   /* [32][520] */
    __nv_bfloat16* bWl = (__nv_bfloat16*)(smraw + OFF_BWL);
    __nv_bfloat16* hAh = (__nv_bfloat16*)(smraw + OFF_HAH);   /* [512][40] col_major A */
    __nv_bfloat16* hAl = (__nv_bfloat16*)(smraw + OFF_HAL);
    float*         scr = (float*)(smraw + OFF_SCR);           /* 8 x 320   */

    const int tid = threadIdx.x;
    const int dir = blockIdx.x >> 6;
    const int dd  = blockIdx.x & 63;
    const int wl  = tid >> 5;              /* warp = local hid j          */
    const int b   = tid & 31;
    const int hid = dd * 8 + wl;

    const float* xg = dir ? xgB : xgF;
    const __nv_bfloat16* Wh = dir ? WBh : WFh;
    const __nv_bfloat16* Wl = dir ? WBl : WFl;

    /* load CTA's 32 weight rows (hi+lo) into SMEM once                */
    {
        const uint4* srcH = (const uint4*)(Wh + (size_t)dd * 32 * H_);
        const uint4* srcL = (const uint4*)(Wl + (size_t)dd * 32 * H_);
        for (int i = tid; i < 2048; i += 256) {
            int r  = i >> 6;
            int ch = i & 63;
            ((uint4*)bWh)[r * 65 + ch] = srcH[i];
            ((uint4*)bWl)[r * 65 + ch] = srcL[i];
        }
    }
    __syncthreads();

    /* warp tile assignment */
    const int p  = wl >> 1;
    const int mt = p >> 1;
    const int nt = p & 1;
    const int q  = wl & 1;
    const __nv_bfloat16* pAh = hAh + mt * 16;
    const __nv_bfloat16* pAl = hAl + mt * 16;
    const __nv_bfloat16* pBh = bWh + nt * 16 * LDB;
    const __nv_bfloat16* pBl = bWl + nt * 16 * LDB;

    float c = 0.0f;

    /* prefetch xg for step 0 */
    const int t_first = dir ? (T_ - 1) : 0;
    const float* xr0 = xg + ((size_t)t_first * G4 + hid) * 32 + b;
    float p0 = xr0[0 * H_ * 32];
    float p1 = xr0[1 * H_ * 32];
    float p2 = xr0[2 * H_ * 32];
    float p3 = xr0[3 * H_ * 32];

    for (int s = 0; s < T_; s++) {
        const int t = dir ? (T_ - 1 - s) : s;
        float a0 = p0, a1 = p1, a2 = p2, a3 = p3;

        if (s > 0) {
            /* stage prev h [512][32] bf16 hi/lo -> SMEM ldm 40 (ldcg) */
            const int par = (s - 1) & 1;
            const uint4* srcH = (const uint4*)g_hbfH[dir][par];
            const uint4* srcL = (const uint4*)g_hbfL[dir][par];
            for (int i = tid; i < 2048; i += 256) {
                int k  = i >> 2;
                int ch = i & 3;
                ((uint4*)hAh)[k * 5 + ch] = __ldcg(srcH + i);
                ((uint4*)hAl)[k * 5 + ch] = __ldcg(srcL + i);
            }
            __syncthreads();

            wmma::fragment<wmma::accumulator, 16, 16, 16, float> facc;
            wmma::fill_fragment(facc, 0.0f);
            #pragma unroll 4
            for (int kt = 0; kt < 16; kt++) {
                const int ko = (q * 16 + kt) * 16;
                wmma::fragment<wmma::matrix_a, 16, 16, 16, __nv_bfloat16,
                               wmma::col_major> fah, fal;
                wmma::fragment<wmma::matrix_b, 16, 16, 16, __nv_bfloat16,
                               wmma::col_major> fbh, fbl;
                wmma::load_matrix_sync(fah, pAh + (size_t)ko * LDA, LDA);
                wmma::load_matrix_sync(fal, pAl + (size_t)ko * LDA, LDA);
                wmma::load_matrix_sync(fbh, pBh + ko, LDB);
                wmma::load_matrix_sync(fbl, pBl + ko, LDB);
                wmma::mma_sync(facc, fah, fbh, facc);
                wmma::mma_sync(facc, fah, fbl, facc);
                wmma::mma_sync(facc, fal, fbh, facc);
            }
            wmma::store_matrix_sync(scr + wl * 320, facc, 20, wmma::mem_row_major);
            __syncthreads();

            /* gather: thread (b, wl) sums 2 k-half partials per gate  */
            const int mt2 = b >> 4;
            const int rr  = b & 15;
            #pragma unroll
            for (int g = 0; g < 4; g++) {
                const int p2 = mt2 * 2 + (g >> 1);
                const int cc = rr * 20 + (g & 1) * 8 + wl;
                float pa = scr[(p2 * 2 + 0) * 320 + cc]
                         + scr[(p2 * 2 + 1) * 320 + cc];
                if      (g == 0) a0 += pa;
                else if (g == 1) a1 += pa;
                else if (g == 2) a2 += pa;
                else             a3 += pa;
            }
        }

        float ig = sigmoidf_(a0);
        float fg = sigmoidf_(a1);
        float gg = tanhf(a2);
        float og = sigmoidf_(a3);
        c = fg * c + ig * gg;
        float h = og * tanhf(c);

        /* publish h as bf16 hi/lo [k=hid][b] (coalesced per warp)     */
        __nv_bfloat16 hh, hl;
        bf16_split(h, hh, hl);
        const int par = s & 1;
        g_hbfH[dir][par][hid * 32 + b] = hh;
        g_hbfL[dir][par][hid * 32 + b] = hl;

        if (writeSplit) {
            size_t oi = ((size_t)(t * B_ + b)) * (2 * H_) + dir * H_ + hid;
            oAh[oi] = hh;
            oAl[oi] = hl;
        } else {
            outf[(size_t)(b * T_ + t) * (2 * H_) + dir * H_ + hid] = h;
        }

        if (s != T_ - 1) {
            const int tn = dir ? (T_ - 2 - s) : (s + 1);
            const float* xr = xg + ((size_t)tn * G4 + hid) * 32 + b;
            p0 = xr[0 * H_ * 32];
            p1 = xr[1 * H_ * 32];
            p2 = xr[2 * H_ * 32];
            p3 = xr[3 * H_ * 32];
            grid_barrier_dir(dir);
        }
    }
}

/* ------------------------------------------------------------------ */
/* Host launcher                                                      */
/* ------------------------------------------------------------------ */
extern "C" void kernel_launch(void* const* d_in, const int* in_sizes, int n_in,
                              void* d_out, int out_size)
{
    const float* x     = (const float*)d_in[0];
    const float* wih0f = (const float*)d_in[1];
    const float* whh0f = (const float*)d_in[2];
    const float* b0f   = (const float*)d_in[3];
    const float* wih0b = (const float*)d_in[4];
    const float* whh0b = (const float*)d_in[5];
    const float* b0b   = (const float*)d_in[6];
    const float* wih1f = (const float*)d_in[7];
    const float* whh1f = (const float*)d_in[8];
    const float* b1f   = (const float*)d_in[9];
    const float* wih1b = (const float*)d_in[10];
    const float* whh1b = (const float*)d_in[11];
    const float* b1b   = (const float*)d_in[12];

    float *xgF, *xgB;
    __nv_bfloat16 *ah0, *al0, *ah1, *al1, *wsp0, *wsp1, *wpkH, *wpkL;
    cudaGetSymbolAddress((void**)&xgF,  g_xgF);
    cudaGetSymbolAddress((void**)&xgB,  g_xgB);
    cudaGetSymbolAddress((void**)&ah0,  g_Ah0);
    cudaGetSymbolAddress((void**)&al0,  g_Al0);
    cudaGetSymbolAddress((void**)&ah1,  g_Ah1);
    cudaGetSymbolAddress((void**)&al1,  g_Al1);
    cudaGetSymbolAddress((void**)&wsp0, g_Wsp0);
    cudaGetSymbolAddress((void**)&wsp1, g_Wsp1);
    cudaGetSymbolAddress((void**)&wpkH, g_WpkH);
    cudaGetSymbolAddress((void**)&wpkL, g_WpkL);

    const size_t WS0  = (size_t)G4 * 512;
    const size_t WS1  = (size_t)G4 * 1024;
    const size_t WPK  = (size_t)G4 * H_;
    const int GEMM_SMEM = 49152 + 8 * 320 * 4;
    cudaFuncSetAttribute(lstm_rec_wmma,
                         cudaFuncAttributeMaxDynamicSharedMemorySize, REC_SMEM);
    cudaFuncSetAttribute(gemm_wmma_kernel,
                         cudaFuncAttributeMaxDynamicSharedMemorySize, GEMM_SMEM);

    dim3 tb(32, 8);
    dim3 gg(G4 / 128, 8192 / 128);

    /* order: launch idx 3 = gemm_wmma (ncu captures launch #3)        */
    pack_whh4<<<dim3(64, 16, 4), tb>>>(whh0f, whh0b, whh1f, whh1b);          /*0*/
    split_x_kernel<<<16384, 256>>>(x, ah0, al0);                             /*1*/
    transpose_split_w<<<dim3(64, 16), tb>>>(wih0f, wsp0 + 0 * WS0,
                                            wsp0 + 1 * WS0, 512);            /*2*/
    gemm_wmma_kernel<<<gg, 256, GEMM_SMEM>>>(ah0, al0,
        wsp0 + 0 * WS0, wsp0 + 1 * WS0, b0f, xgF, 512);                      /*3*/
    transpose_split_w<<<dim3(64, 16), tb>>>(wih0b, wsp0 + 2 * WS0,
                                            wsp0 + 3 * WS0, 512);            /*4*/
    gemm_wmma_kernel<<<gg, 256, GEMM_SMEM>>>(ah0, al0,
        wsp0 + 2 * WS0, wsp0 + 3 * WS0, b0b, xgB, 512);                      /*5*/
    lstm_rec_wmma<<<NREC_CTAS, 256, REC_SMEM>>>(
        xgF, xgB,
        wpkH + 0 * WPK, wpkL + 0 * WPK,     /* layer0 fwd */
        wpkH + 1 * WPK, wpkL + 1 * WPK,     /* layer0 bwd */
        ah1, al1, nullptr, 1);                                               /*6*/
    transpose_split_w<<<dim3(64, 32), tb>>>(wih1f, wsp1 + 0 * WS1,
                                            wsp1 + 1 * WS1, 1024);           /*7*/
    transpose_split_w<<<dim3(64, 32), tb>>>(wih1b, wsp1 + 2 * WS1,
                                            wsp1 + 3 * WS1, 1024);           /*8*/
    gemm_wmma_kernel<<<gg, 256, GEMM_SMEM>>>(ah1, al1,
        wsp1 + 0 * WS1, wsp1 + 1 * WS1, b1f, xgF, 1024);                     /*9*/
    gemm_wmma_kernel<<<gg, 256, GEMM_SMEM>>>(ah1, al1,
        wsp1 + 2 * WS1, wsp1 + 3 * WS1, b1b, xgB, 1024);                     /*10*/
    lstm_rec_wmma<<<NREC_CTAS, 256, REC_SMEM>>>(
        xgF, xgB,
        wpkH + 2 * WPK, wpkL + 2 * WPK,     /* layer1 fwd */
        wpkH + 3 * WPK, wpkL + 3 * WPK,     /* layer1 bwd */
        nullptr, nullptr, (float*)d_out, 0);                                 /*11*/
}

// round 11
// speedup vs baseline: 2.5243x; 1.0626x over previous
#include <cuda_runtime.h>
#include <cuda_bf16.h>
#include <mma.h>
#include <math.h>
#include <stdint.h>

using namespace nvcuda;

#define B_   32
#define T_   256
#define IN_  512
#define H_   512
#define G4   2048   /* 4*H */
#define NREC_CTAS 128

/* ------------------------------------------------------------------ */
/* Static device scratch                                              */
/* ------------------------------------------------------------------ */
__device__ float g_xgF[(size_t)T_ * B_ * G4];          /* 64 MB, [t][col][b] */
__device__ float g_xgB[(size_t)T_ * B_ * G4];          /* 64 MB, [t][col][b] */
__device__ unsigned g_barCount[2][32];
__device__ unsigned g_barGen[2][32];

/* recurrent h state, bf16 hi/lo, layout [k=hid][b], double-buffered  */
__device__ __nv_bfloat16 g_hbfH[2][2][H_ * B_];
__device__ __nv_bfloat16 g_hbfL[2][2][H_ * B_];

/* bf16 hi/lo split operands for the tensor-core input GEMMs */
__device__ __nv_bfloat16 g_Ah0[(size_t)8192 * 512];
__device__ __nv_bfloat16 g_Al0[(size_t)8192 * 512];
__device__ __nv_bfloat16 g_Ah1[(size_t)8192 * 1024];
__device__ __nv_bfloat16 g_Al1[(size_t)8192 * 1024];
__device__ __nv_bfloat16 g_Wsp0[2][2][(size_t)G4 * 512];
__device__ __nv_bfloat16 g_Wsp1[2][2][(size_t)G4 * 1024];

/* packed recurrent weights: [layer*2+dir][hi/lo][col'=dd*32+g*8+j][k] */
__device__ __nv_bfloat16 g_WpkH[4][(size_t)G4 * H_];
__device__ __nv_bfloat16 g_WpkL[4][(size_t)G4 * H_];

/* ------------------------------------------------------------------ */
__device__ __forceinline__ void grid_barrier_dir(int dir)
{
    __threadfence();
    __syncthreads();
    if (threadIdx.x == 0) {
        unsigned gen = *((volatile unsigned*)&g_barGen[dir][0]);
        unsigned arrived = atomicAdd(&g_barCount[dir][0], 1u);
        if (arrived == (NREC_CTAS / 2) - 1) {
            atomicExch(&g_barCount[dir][0], 0u);
            __threadfence();
            atomicAdd(&g_barGen[dir][0], 1u);
        } else {
            while (*((volatile unsigned*)&g_barGen[dir][0]) == gen) {
                __nanosleep(32);
            }
        }
    }
    __syncthreads();
    __threadfence();
}

__device__ __forceinline__ float sigmoidf_(float x)
{
    return 1.0f / (1.0f + expf(-x));
}

__device__ __forceinline__ void bf16_split(float v, __nv_bfloat16& h, __nv_bfloat16& l)
{
    h = __float2bfloat16(v);
    l = __float2bfloat16(v - __bfloat162float(h));
}

/* ------------------------------------------------------------------ */
/* x [B][T][IN] fp32 -> Ah/Al [m=t*B+b][k] bf16 hi/lo                 */
/* ------------------------------------------------------------------ */
__global__ void split_x_kernel(const float* __restrict__ x,
                               __nv_bfloat16* __restrict__ Ah,
                               __nv_bfloat16* __restrict__ Al)
{
    int idx = blockIdx.x * blockDim.x + threadIdx.x;
    int m = idx >> 9;
    int k = idx & 511;
    int b = m & 31;
    int t = m >> 5;
    float v = x[((size_t)b * T_ + t) * IN_ + k];
    __nv_bfloat16 h, l;
    bf16_split(v, h, l);
    Ah[idx] = h;
    Al[idx] = l;
}

/* ------------------------------------------------------------------ */
/* W_ih [Din][4H] fp32 -> Wh/Wl [4H][Din] bf16 hi/lo (transposed)     */
/* ------------------------------------------------------------------ */
__global__ void transpose_split_w(const float* __restrict__ W,
                                  __nv_bfloat16* __restrict__ Wh,
                                  __nv_bfloat16* __restrict__ Wl, int Din)
{
    __shared__ float tile[32][33];
    int x  = blockIdx.x * 32 + threadIdx.x;
    int y0 = blockIdx.y * 32;
    #pragma unroll
    for (int i = threadIdx.y; i < 32; i += 8)
        tile[i][threadIdx.x] = W[(size_t)(y0 + i) * G4 + x];
    __syncthreads();
    int k  = y0 + threadIdx.x;
    int n0 = blockIdx.x * 32;
    #pragma unroll
    for (int i = threadIdx.y; i < 32; i += 8) {
        float v = tile[threadIdx.x][i];
        __nv_bfloat16 h, l;
        bf16_split(v, h, l);
        Wh[(size_t)(n0 + i) * Din + k] = h;
        Wl[(size_t)(n0 + i) * Din + k] = l;
    }
}

/* ------------------------------------------------------------------ */
/* Pack all 4 W_hh [H,4H] -> bf16 hi/lo [col'][k], col'=dd*32+g*8+j   */
/* ------------------------------------------------------------------ */
__global__ void pack_whh4(const float* __restrict__ w0,
                          const float* __restrict__ w1,
                          const float* __restrict__ w2,
                          const float* __restrict__ w3)
{
    const int z = blockIdx.z;
    const float* W = (z == 0) ? w0 : (z == 1) ? w1 : (z == 2) ? w2 : w3;
    __nv_bfloat16* Wh = g_WpkH[z];
    __nv_bfloat16* Wl = g_WpkL[z];

    __shared__ float tile[32][33];
    const int tx = threadIdx.x;
    const int k0 = blockIdx.y * 32;
    const int cp0 = blockIdx.x * 32;
    const int c = ((tx >> 3) & 3) * 512 + blockIdx.x * 8 + (tx & 7);
    #pragma unroll
    for (int i = threadIdx.y; i < 32; i += 8)
        tile[i][tx] = W[(size_t)(k0 + i) * G4 + c];
    __syncthreads();
    #pragma unroll
    for (int i = threadIdx.y; i < 32; i += 8) {
        float v = tile[tx][i];
        __nv_bfloat16 h, l;
        bf16_split(v, h, l);
        Wh[(size_t)(cp0 + i) * H_ + k0 + tx] = h;
        Wl[(size_t)(cp0 + i) * H_ + k0 + tx] = l;
    }
}

/* ------------------------------------------------------------------ */
/* WMMA input GEMM, split-bf16 (3 products), fp32 accumulate.         */
/* (unchanged from R10 — proven)                                      */
/* ------------------------------------------------------------------ */
__global__ void __launch_bounds__(256)
gemm_wmma_kernel(const __nv_bfloat16* __restrict__ Ah,
                 const __nv_bfloat16* __restrict__ Al,
                 const __nv_bfloat16* __restrict__ Bh,
                 const __nv_bfloat16* __restrict__ Bl,
                 const float* __restrict__ bias,
                 float* __restrict__ out, int Din)
{
    extern __shared__ char smraw[];
    __nv_bfloat16* smb = (__nv_bfloat16*)smraw;
    float* csc = (float*)(smraw + 49152);

    const int tid  = threadIdx.x;
    const int lane = tid & 31;
    const int wid  = tid >> 5;
    const int wm   = wid >> 2;
    const int wn   = wid & 3;
    const int m0   = blockIdx.y * 128;
    const int col0 = blockIdx.x * 128;

    const int lr = tid >> 1;
    const int lh = tid & 1;
    const __nv_bfloat16* gAh = Ah + (size_t)(m0 + lr) * Din + lh * 8;
    const __nv_bfloat16* gAl = Al + (size_t)(m0 + lr) * Din + lh * 8;
    const __nv_bfloat16* gBh = Bh + (size_t)(col0 + lr) * Din + lh * 8;
    const __nv_bfloat16* gBl = Bl + (size_t)(col0 + lr) * Din + lh * 8;
    const int soff = lr * 24 + lh * 8;

    wmma::fragment<wmma::accumulator, 16, 16, 16, float> acc[4][2];
    #pragma unroll
    for (int i = 0; i < 4; i++)
        #pragma unroll
        for (int j = 0; j < 2; j++)
            wmma::fill_fragment(acc[i][j], 0.0f);

    uint4 rAh = *(const uint4*)gAh;
    uint4 rAl = *(const uint4*)gAl;
    uint4 rBh = *(const uint4*)gBh;
    uint4 rBl = *(const uint4*)gBl;

    *(uint4*)(smb + 0 * 12288 + 0 * 3072 + soff) = rAh;
    *(uint4*)(smb + 0 * 12288 + 1 * 3072 + soff) = rAl;
    *(uint4*)(smb + 0 * 12288 + 2 * 3072 + soff) = rBh;
    *(uint4*)(smb + 0 * 12288 + 3 * 3072 + soff) = rBl;
    __syncthreads();

    const int Nk = Din >> 4;
    for (int kt = 0; kt < Nk; kt++) {
        const int cur = kt & 1;
        const int nxt = cur ^ 1;

        if (kt + 1 < Nk) {
            const int ko = (kt + 1) << 4;
            rAh = *(const uint4*)(gAh + ko);
            rAl = *(const uint4*)(gAl + ko);
            rBh = *(const uint4*)(gBh + ko);
            rBl = *(const uint4*)(gBl + ko);
        }

        const __nv_bfloat16* sAh = smb + cur * 12288;
        const __nv_bfloat16* sAl = sAh + 3072;
        const __nv_bfloat16* sBh = sAh + 6144;
        const __nv_bfloat16* sBl = sAh + 9216;

        wmma::fragment<wmma::matrix_b, 16, 16, 16, __nv_bfloat16,
                       wmma::col_major> fbh[2], fbl[2];
        #pragma unroll
        for (int nt = 0; nt < 2; nt++) {
            const int nl = wn * 32 + nt * 16;
            wmma::load_matrix_sync(fbh[nt], sBh + nl * 24, 24);
            wmma::load_matrix_sync(fbl[nt], sBl + nl * 24, 24);
        }

        #pragma unroll
        for (int mt = 0; mt < 4; mt++) {
            const int ml = wm * 64 + mt * 16;
            wmma::fragment<wmma::matrix_a, 16, 16, 16, __nv_bfloat16,
                           wmma::row_major> fah, fal;
            wmma::load_matrix_sync(fah, sAh + ml * 24, 24);
            wmma::load_matrix_sync(fal, sAl + ml * 24, 24);
            #pragma unroll
            for (int nt = 0; nt < 2; nt++) {
                wmma::mma_sync(acc[mt][nt], fah, fbh[nt], acc[mt][nt]);
                wmma::mma_sync(acc[mt][nt], fah, fbl[nt], acc[mt][nt]);
                wmma::mma_sync(acc[mt][nt], fal, fbh[nt], acc[mt][nt]);
            }
        }

        if (kt + 1 < Nk) {
            *(uint4*)(smb + nxt * 12288 + 0 * 3072 + soff) = rAh;
            *(uint4*)(smb + nxt * 12288 + 1 * 3072 + soff) = rAl;
            *(uint4*)(smb + nxt * 12288 + 2 * 3072 + soff) = rBh;
            *(uint4*)(smb + nxt * 12288 + 3 * 3072 + soff) = rBl;
        }
        __syncthreads();
    }

    float* myscr = csc + wid * 320;
    const int r  = lane & 15;
    const int ch = lane >> 4;
    #pragma unroll
    for (int mt = 0; mt < 4; mt++) {
        const int m1 = m0 + wm * 64 + mt * 16;
        const int t1 = m1 >> 5;
        const int b1 = (m1 & 31) + r;
        #pragma unroll
        for (int nt = 0; nt < 2; nt++) {
            wmma::store_matrix_sync(myscr, acc[mt][nt], 20, wmma::mem_row_major);
            __syncwarp();
            #pragma unroll
            for (int q = 0; q < 8; q++) {
                const int cc  = ch * 8 + q;
                const int col = col0 + wn * 32 + nt * 16 + cc;
                out[((size_t)t1 * G4 + col) * 32 + b1] =
                    myscr[r * 20 + cc] + __ldg(&bias[col]);
            }
            __syncwarp();
        }
    }
}

/* ------------------------------------------------------------------ */
/* WMMA persistent LSTM recurrence with REGISTER-RESIDENT weight      */
/* fragments. Weights pass through SMEM once; their SMEM region is    */
/* then reused for h staging + scratch (REC_SMEM 92160 B).            */
/* Warp wl: tile pair p=wl>>1 (mt=p>>1, nt=p&1), k-half q=wl&1.       */
/* ------------------------------------------------------------------ */
#define LDA 40
#define LDB 520
#define OFF_HAL 40960
#define OFF_SCR 81920
#define REC_SMEM 92160

__global__ void __launch_bounds__(256, 1)
lstm_rec_wmma(const float* __restrict__ xgF, const float* __restrict__ xgB,
              const __nv_bfloat16* __restrict__ WFh, const __nv_bfloat16* __restrict__ WFl,
              const __nv_bfloat16* __restrict__ WBh, const __nv_bfloat16* __restrict__ WBl,
              __nv_bfloat16* __restrict__ oAh, __nv_bfloat16* __restrict__ oAl,
              float* __restrict__ outf, int writeSplit)
{
    extern __shared__ char smraw[];
    /* phase 1 (init only): sWh @0 [32][520], sWl @33280 [32][520]     */
    __nv_bfloat16* sWh = (__nv_bfloat16*)smraw;
    __nv_bfloat16* sWl = (__nv_bfloat16*)(smraw + 33280);
    /* steady state (after frag extraction): reuses the same bytes     */
    __nv_bfloat16* hAh = (__nv_bfloat16*)smraw;               /* [512][40] */
    __nv_bfloat16* hAl = (__nv_bfloat16*)(smraw + OFF_HAL);   /* [512][40] */
    float*         scr = (float*)(smraw + OFF_SCR);           /* 8 x 320   */

    const int tid = threadIdx.x;
    const int dir = blockIdx.x >> 6;
    const int dd  = blockIdx.x & 63;
    const int wl  = tid >> 5;
    const int b   = tid & 31;
    const int hid = dd * 8 + wl;

    const float* xg = dir ? xgB : xgF;
    const __nv_bfloat16* Wh = dir ? WBh : WFh;
    const __nv_bfloat16* Wl = dir ? WBl : WFl;

    /* phase 1: W rows -> SMEM */
    {
        const uint4* srcH = (const uint4*)(Wh + (size_t)dd * 32 * H_);
        const uint4* srcL = (const uint4*)(Wl + (size_t)dd * 32 * H_);
        for (int i = tid; i < 2048; i += 256) {
            int r  = i >> 6;
            int ch = i & 63;
            ((uint4*)sWh)[r * 65 + ch] = srcH[i];
            ((uint4*)sWl)[r * 65 + ch] = srcL[i];
        }
    }
    __syncthreads();

    /* warp tile assignment */
    const int p  = wl >> 1;
    const int mt = p >> 1;
    const int nt = p & 1;
    const int q  = wl & 1;

    /* extract this warp's 32 weight fragments into registers          */
    wmma::fragment<wmma::matrix_b, 16, 16, 16, __nv_bfloat16,
                   wmma::col_major> fbh[16], fbl[16];
    #pragma unroll
    for (int kt = 0; kt < 16; kt++) {
        const int ko = (q * 16 + kt) * 16;
        wmma::load_matrix_sync(fbh[kt], sWh + nt * 16 * LDB + ko, LDB);
        wmma::load_matrix_sync(fbl[kt], sWl + nt * 16 * LDB + ko, LDB);
    }
    __syncthreads();   /* all warps done with W SMEM; region now free  */

    const __nv_bfloat16* pAh = hAh + mt * 16;
    const __nv_bfloat16* pAl = hAl + mt * 16;

    float c = 0.0f;

    /* prefetch xg for step 0 */
    const int t_first = dir ? (T_ - 1) : 0;
    const float* xr0 = xg + ((size_t)t_first * G4 + hid) * 32 + b;
    float p0 = xr0[0 * H_ * 32];
    float p1 = xr0[1 * H_ * 32];
    float p2 = xr0[2 * H_ * 32];
    float p3 = xr0[3 * H_ * 32];

    for (int s = 0; s < T_; s++) {
        const int t = dir ? (T_ - 1 - s) : s;
        float a0 = p0, a1 = p1, a2 = p2, a3 = p3;

        if (s > 0) {
            /* stage prev h [512][32] bf16 hi/lo -> SMEM ldm 40        */
            const int par = (s - 1) & 1;
            const uint4* srcH = (const uint4*)g_hbfH[dir][par];
            const uint4* srcL = (const uint4*)g_hbfL[dir][par];
            for (int i = tid; i < 2048; i += 256) {
                int k  = i >> 2;
                int ch = i & 3;
                ((uint4*)hAh)[k * 5 + ch] = __ldcg(srcH + i);
                ((uint4*)hAl)[k * 5 + ch] = __ldcg(srcL + i);
            }
            __syncthreads();

            wmma::fragment<wmma::accumulator, 16, 16, 16, float> facc;
            wmma::fill_fragment(facc, 0.0f);
            #pragma unroll
            for (int kt = 0; kt < 16; kt++) {
                const int ko = (q * 16 + kt) * 16;
                wmma::fragment<wmma::matrix_a, 16, 16, 16, __nv_bfloat16,
                               wmma::col_major> fah, fal;
                wmma::load_matrix_sync(fah, pAh + (size_t)ko * LDA, LDA);
                wmma::load_matrix_sync(fal, pAl + (size_t)ko * LDA, LDA);
                wmma::mma_sync(facc, fah, fbh[kt], facc);
                wmma::mma_sync(facc, fah, fbl[kt], facc);
                wmma::mma_sync(facc, fal, fbh[kt], facc);
            }
            __syncthreads();   /* hA reads done before scr overwrites  */
            wmma::store_matrix_sync(scr + wl * 320, facc, 20, wmma::mem_row_major);
            __syncthreads();

            /* gather: thread (b, wl) sums 2 k-half partials per gate  */
            const int mt2 = b >> 4;
            const int rr  = b & 15;
            #pragma unroll
            for (int g = 0; g < 4; g++) {
                const int p2 = mt2 * 2 + (g >> 1);
                const int cc = rr * 20 + (g & 1) * 8 + wl;
                float pa = scr[(p2 * 2 + 0) * 320 + cc]
                         + scr[(p2 * 2 + 1) * 320 + cc];
                if      (g == 0) a0 += pa;
                else if (g == 1) a1 += pa;
                else if (g == 2) a2 += pa;
                else             a3 += pa;
            }
        }

        float ig = sigmoidf_(a0);
        float fg = sigmoidf_(a1);
        float gg = tanhf(a2);
        float og = sigmoidf_(a3);
        c = fg * c + ig * gg;
        float h = og * tanhf(c);

        __nv_bfloat16 hh, hl;
        bf16_split(h, hh, hl);
        const int par = s & 1;
        g_hbfH[dir][par][hid * 32 + b] = hh;
        g_hbfL[dir][par][hid * 32 + b] = hl;

        if (writeSplit) {
            size_t oi = ((size_t)(t * B_ + b)) * (2 * H_) + dir * H_ + hid;
            oAh[oi] = hh;
            oAl[oi] = hl;
        } else {
            outf[(size_t)(b * T_ + t) * (2 * H_) + dir * H_ + hid] = h;
        }

        if (s != T_ - 1) {
            const int tn = dir ? (T_ - 2 - s) : (s + 1);
            const float* xr = xg + ((size_t)tn * G4 + hid) * 32 + b;
            p0 = xr[0 * H_ * 32];
            p1 = xr[1 * H_ * 32];
            p2 = xr[2 * H_ * 32];
            p3 = xr[3 * H_ * 32];
            grid_barrier_dir(dir);
        }
    }
}

/* ------------------------------------------------------------------ */
/* Host launcher                                                      */
/* ------------------------------------------------------------------ */
extern "C" void kernel_launch(void* const* d_in, const int* in_sizes, int n_in,
                              void* d_out, int out_size)
{
    const float* x     = (const float*)d_in[0];
    const float* wih0f = (const float*)d_in[1];
    const float* whh0f = (const float*)d_in[2];
    const float* b0f   = (const float*)d_in[3];
    const float* wih0b = (const float*)d_in[4];
    const float* whh0b = (const float*)d_in[5];
    const float* b0b   = (const float*)d_in[6];
    const float* wih1f = (const float*)d_in[7];
    const float* whh1f = (const float*)d_in[8];
    const float* b1f   = (const float*)d_in[9];
    const float* wih1b = (const float*)d_in[10];
    const float* whh1b = (const float*)d_in[11];
    const float* b1b   = (const float*)d_in[12];

    float *xgF, *xgB;
    __nv_bfloat16 *ah0, *al0, *ah1, *al1, *wsp0, *wsp1, *wpkH, *wpkL;
    cudaGetSymbolAddress((void**)&xgF,  g_xgF);
    cudaGetSymbolAddress((void**)&xgB,  g_xgB);
    cudaGetSymbolAddress((void**)&ah0,  g_Ah0);
    cudaGetSymbolAddress((void**)&al0,  g_Al0);
    cudaGetSymbolAddress((void**)&ah1,  g_Ah1);
    cudaGetSymbolAddress((void**)&al1,  g_Al1);
    cudaGetSymbolAddress((void**)&wsp0, g_Wsp0);
    cudaGetSymbolAddress((void**)&wsp1, g_Wsp1);
    cudaGetSymbolAddress((void**)&wpkH, g_WpkH);
    cudaGetSymbolAddress((void**)&wpkL, g_WpkL);

    const size_t WS0  = (size_t)G4 * 512;
    const size_t WS1  = (size_t)G4 * 1024;
    const size_t WPK  = (size_t)G4 * H_;
    const int GEMM_SMEM = 49152 + 8 * 320 * 4;
    cudaFuncSetAttribute(lstm_rec_wmma,
                         cudaFuncAttributeMaxDynamicSharedMemorySize, REC_SMEM);
    cudaFuncSetAttribute(gemm_wmma_kernel,
                         cudaFuncAttributeMaxDynamicSharedMemorySize, GEMM_SMEM);

    dim3 tb(32, 8);
    dim3 gg(G4 / 128, 8192 / 128);

    pack_whh4<<<dim3(64, 16, 4), tb>>>(whh0f, whh0b, whh1f, whh1b);          /*0*/
    split_x_kernel<<<16384, 256>>>(x, ah0, al0);                             /*1*/
    transpose_split_w<<<dim3(64, 16), tb>>>(wih0f, wsp0 + 0 * WS0,
                                            wsp0 + 1 * WS0, 512);            /*2*/
    gemm_wmma_kernel<<<gg, 256, GEMM_SMEM>>>(ah0, al0,
        wsp0 + 0 * WS0, wsp0 + 1 * WS0, b0f, xgF, 512);                      /*3*/
    transpose_split_w<<<dim3(64, 16), tb>>>(wih0b, wsp0 + 2 * WS0,
                                            wsp0 + 3 * WS0, 512);            /*4*/
    gemm_wmma_kernel<<<gg, 256, GEMM_SMEM>>>(ah0, al0,
        wsp0 + 2 * WS0, wsp0 + 3 * WS0, b0b, xgB, 512);                      /*5*/
    lstm_rec_wmma<<<NREC_CTAS, 256, REC_SMEM>>>(
        xgF, xgB,
        wpkH + 0 * WPK, wpkL + 0 * WPK,
        wpkH + 1 * WPK, wpkL + 1 * WPK,
        ah1, al1, nullptr, 1);                                               /*6*/
    transpose_split_w<<<dim3(64, 32), tb>>>(wih1f, wsp1 + 0 * WS1,
                                            wsp1 + 1 * WS1, 1024);           /*7*/
    transpose_split_w<<<dim3(64, 32), tb>>>(wih1b, wsp1 + 2 * WS1,
                                            wsp1 + 3 * WS1, 1024);           /*8*/
    gemm_wmma_kernel<<<gg, 256, GEMM_SMEM>>>(ah1, al1,
        wsp1 + 0 * WS1, wsp1 + 1 * WS1, b1f, xgF, 1024);                     /*9*/
    gemm_wmma_kernel<<<gg, 256, GEMM_SMEM>>>(ah1, al1,
        wsp1 + 2 * WS1, wsp1 + 3 * WS1, b1b, xgB, 1024);                     /*10*/
    lstm_rec_wmma<<<NREC_CTAS, 256, REC_SMEM>>>(
        xgF, xgB,
        wpkH + 2 * WPK, wpkL + 2 * WPK,
        wpkH + 3 * WPK, wpkL + 3 * WPK,
        nullptr, nullptr, (float*)d_out, 0);                                 /*11*/
}

// round 12
// speedup vs baseline: 2.5422x; 1.0071x over previous
#include <cuda_runtime.h>
#include <cuda_bf16.h>
#include <mma.h>
#include <math.h>
#include <stdint.h>

using namespace nvcuda;

#define B_   32
#define T_   256
#define IN_  512
#define H_   512
#define G4   2048   /* 4*H */
#define NREC_CTAS 128

/* ------------------------------------------------------------------ */
/* Static device scratch                                              */
/* ------------------------------------------------------------------ */
__device__ float g_xgF[(size_t)T_ * B_ * G4];          /* 64 MB, [t][col][b] */
__device__ float g_xgB[(size_t)T_ * B_ * G4];          /* 64 MB, [t][col][b] */
__device__ unsigned g_barCount[2][32];
__device__ unsigned g_barGen[2][32];

/* recurrent h state, bf16 hi/lo, layout [k=hid][b], double-buffered  */
__device__ __nv_bfloat16 g_hbfH[2][2][H_ * B_];
__device__ __nv_bfloat16 g_hbfL[2][2][H_ * B_];

/* bf16 hi/lo split operands for the tensor-core input GEMMs */
__device__ __nv_bfloat16 g_Ah0[(size_t)8192 * 512];
__device__ __nv_bfloat16 g_Al0[(size_t)8192 * 512];
__device__ __nv_bfloat16 g_Ah1[(size_t)8192 * 1024];
__device__ __nv_bfloat16 g_Al1[(size_t)8192 * 1024];
__device__ __nv_bfloat16 g_Wsp0[2][2][(size_t)G4 * 512];
__device__ __nv_bfloat16 g_Wsp1[2][2][(size_t)G4 * 1024];

/* packed recurrent weights: [layer*2+dir][hi/lo][col'=dd*32+g*8+j][k] */
__device__ __nv_bfloat16 g_WpkH[4][(size_t)G4 * H_];
__device__ __nv_bfloat16 g_WpkL[4][(size_t)G4 * H_];

/* ------------------------------------------------------------------ */
__device__ __forceinline__ void grid_barrier_dir(int dir)
{
    __threadfence();
    __syncthreads();
    if (threadIdx.x == 0) {
        unsigned gen = *((volatile unsigned*)&g_barGen[dir][0]);
        unsigned arrived = atomicAdd(&g_barCount[dir][0], 1u);
        if (arrived == (NREC_CTAS / 2) - 1) {
            atomicExch(&g_barCount[dir][0], 0u);
            __threadfence();
            atomicAdd(&g_barGen[dir][0], 1u);
        } else {
            while (*((volatile unsigned*)&g_barGen[dir][0]) == gen) {
                __nanosleep(32);
            }
        }
    }
    __syncthreads();
    __threadfence();
}

__device__ __forceinline__ float sigmoidf_(float x)
{
    return 1.0f / (1.0f + expf(-x));
}

__device__ __forceinline__ void bf16_split(float v, __nv_bfloat16& h, __nv_bfloat16& l)
{
    h = __float2bfloat16(v);
    l = __float2bfloat16(v - __bfloat162float(h));
}

/* ------------------------------------------------------------------ */
/* x [B][T][IN] fp32 -> Ah/Al [m=t*B+b][k] bf16 hi/lo                 */
/* ------------------------------------------------------------------ */
__global__ void split_x_kernel(const float* __restrict__ x,
                               __nv_bfloat16* __restrict__ Ah,
                               __nv_bfloat16* __restrict__ Al)
{
    int idx = blockIdx.x * blockDim.x + threadIdx.x;
    int m = idx >> 9;
    int k = idx & 511;
    int b = m & 31;
    int t = m >> 5;
    float v = x[((size_t)b * T_ + t) * IN_ + k];
    __nv_bfloat16 h, l;
    bf16_split(v, h, l);
    Ah[idx] = h;
    Al[idx] = l;
}

/* ------------------------------------------------------------------ */
/* W_ih [Din][4H] fp32 -> Wh/Wl [4H][Din] bf16 hi/lo (transposed)     */
/* ------------------------------------------------------------------ */
__global__ void transpose_split_w(const float* __restrict__ W,
                                  __nv_bfloat16* __restrict__ Wh,
                                  __nv_bfloat16* __restrict__ Wl, int Din)
{
    __shared__ float tile[32][33];
    int x  = blockIdx.x * 32 + threadIdx.x;
    int y0 = blockIdx.y * 32;
    #pragma unroll
    for (int i = threadIdx.y; i < 32; i += 8)
        tile[i][threadIdx.x] = W[(size_t)(y0 + i) * G4 + x];
    __syncthreads();
    int k  = y0 + threadIdx.x;
    int n0 = blockIdx.x * 32;
    #pragma unroll
    for (int i = threadIdx.y; i < 32; i += 8) {
        float v = tile[threadIdx.x][i];
        __nv_bfloat16 h, l;
        bf16_split(v, h, l);
        Wh[(size_t)(n0 + i) * Din + k] = h;
        Wl[(size_t)(n0 + i) * Din + k] = l;
    }
}

/* ------------------------------------------------------------------ */
/* Pack all 4 W_hh [H,4H] -> bf16 hi/lo [col'][k], col'=dd*32+g*8+j   */
/* ------------------------------------------------------------------ */
__global__ void pack_whh4(const float* __restrict__ w0,
                          const float* __restrict__ w1,
                          const float* __restrict__ w2,
                          const float* __restrict__ w3)
{
    const int z = blockIdx.z;
    const float* W = (z == 0) ? w0 : (z == 1) ? w1 : (z == 2) ? w2 : w3;
    __nv_bfloat16* Wh = g_WpkH[z];
    __nv_bfloat16* Wl = g_WpkL[z];

    __shared__ float tile[32][33];
    const int tx = threadIdx.x;
    const int k0 = blockIdx.y * 32;
    const int cp0 = blockIdx.x * 32;
    const int c = ((tx >> 3) & 3) * 512 + blockIdx.x * 8 + (tx & 7);
    #pragma unroll
    for (int i = threadIdx.y; i < 32; i += 8)
        tile[i][tx] = W[(size_t)(k0 + i) * G4 + c];
    __syncthreads();
    #pragma unroll
    for (int i = threadIdx.y; i < 32; i += 8) {
        float v = tile[tx][i];
        __nv_bfloat16 h, l;
        bf16_split(v, h, l);
        Wh[(size_t)(cp0 + i) * H_ + k0 + tx] = h;
        Wl[(size_t)(cp0 + i) * H_ + k0 + tx] = l;
    }
}

/* ------------------------------------------------------------------ */
/* WMMA input GEMM, split-bf16 (3 products), fp32 accumulate.         */
/* (unchanged — proven)                                               */
/* ------------------------------------------------------------------ */
__global__ void __launch_bounds__(256)
gemm_wmma_kernel(const __nv_bfloat16* __restrict__ Ah,
                 const __nv_bfloat16* __restrict__ Al,
                 const __nv_bfloat16* __restrict__ Bh,
                 const __nv_bfloat16* __restrict__ Bl,
                 const float* __restrict__ bias,
                 float* __restrict__ out, int Din)
{
    extern __shared__ char smraw[];
    __nv_bfloat16* smb = (__nv_bfloat16*)smraw;
    float* csc = (float*)(smraw + 49152);

    const int tid  = threadIdx.x;
    const int lane = tid & 31;
    const int wid  = tid >> 5;
    const int wm   = wid >> 2;
    const int wn   = wid & 3;
    const int m0   = blockIdx.y * 128;
    const int col0 = blockIdx.x * 128;

    const int lr = tid >> 1;
    const int lh = tid & 1;
    const __nv_bfloat16* gAh = Ah + (size_t)(m0 + lr) * Din + lh * 8;
    const __nv_bfloat16* gAl = Al + (size_t)(m0 + lr) * Din + lh * 8;
    const __nv_bfloat16* gBh = Bh + (size_t)(col0 + lr) * Din + lh * 8;
    const __nv_bfloat16* gBl = Bl + (size_t)(col0 + lr) * Din + lh * 8;
    const int soff = lr * 24 + lh * 8;

    wmma::fragment<wmma::accumulator, 16, 16, 16, float> acc[4][2];
    #pragma unroll
    for (int i = 0; i < 4; i++)
        #pragma unroll
        for (int j = 0; j < 2; j++)
            wmma::fill_fragment(acc[i][j], 0.0f);

    uint4 rAh = *(const uint4*)gAh;
    uint4 rAl = *(const uint4*)gAl;
    uint4 rBh = *(const uint4*)gBh;
    uint4 rBl = *(const uint4*)gBl;

    *(uint4*)(smb + 0 * 12288 + 0 * 3072 + soff) = rAh;
    *(uint4*)(smb + 0 * 12288 + 1 * 3072 + soff) = rAl;
    *(uint4*)(smb + 0 * 12288 + 2 * 3072 + soff) = rBh;
    *(uint4*)(smb + 0 * 12288 + 3 * 3072 + soff) = rBl;
    __syncthreads();

    const int Nk = Din >> 4;
    for (int kt = 0; kt < Nk; kt++) {
        const int cur = kt & 1;
        const int nxt = cur ^ 1;

        if (kt + 1 < Nk) {
            const int ko = (kt + 1) << 4;
            rAh = *(const uint4*)(gAh + ko);
            rAl = *(const uint4*)(gAl + ko);
            rBh = *(const uint4*)(gBh + ko);
            rBl = *(const uint4*)(gBl + ko);
        }

        const __nv_bfloat16* sAh = smb + cur * 12288;
        const __nv_bfloat16* sAl = sAh + 3072;
        const __nv_bfloat16* sBh = sAh + 6144;
        const __nv_bfloat16* sBl = sAh + 9216;

        wmma::fragment<wmma::matrix_b, 16, 16, 16, __nv_bfloat16,
                       wmma::col_major> fbh[2], fbl[2];
        #pragma unroll
        for (int nt = 0; nt < 2; nt++) {
            const int nl = wn * 32 + nt * 16;
            wmma::load_matrix_sync(fbh[nt], sBh + nl * 24, 24);
            wmma::load_matrix_sync(fbl[nt], sBl + nl * 24, 24);
        }

        #pragma unroll
        for (int mt = 0; mt < 4; mt++) {
            const int ml = wm * 64 + mt * 16;
            wmma::fragment<wmma::matrix_a, 16, 16, 16, __nv_bfloat16,
                           wmma::row_major> fah, fal;
            wmma::load_matrix_sync(fah, sAh + ml * 24, 24);
            wmma::load_matrix_sync(fal, sAl + ml * 24, 24);
            #pragma unroll
            for (int nt = 0; nt < 2; nt++) {
                wmma::mma_sync(acc[mt][nt], fah, fbh[nt], acc[mt][nt]);
                wmma::mma_sync(acc[mt][nt], fah, fbl[nt], acc[mt][nt]);
                wmma::mma_sync(acc[mt][nt], fal, fbh[nt], acc[mt][nt]);
            }
        }

        if (kt + 1 < Nk) {
            *(uint4*)(smb + nxt * 12288 + 0 * 3072 + soff) = rAh;
            *(uint4*)(smb + nxt * 12288 + 1 * 3072 + soff) = rAl;
            *(uint4*)(smb + nxt * 12288 + 2 * 3072 + soff) = rBh;
            *(uint4*)(smb + nxt * 12288 + 3 * 3072 + soff) = rBl;
        }
        __syncthreads();
    }

    float* myscr = csc + wid * 320;
    const int r  = lane & 15;
    const int ch = lane >> 4;
    #pragma unroll
    for (int mt = 0; mt < 4; mt++) {
        const int m1 = m0 + wm * 64 + mt * 16;
        const int t1 = m1 >> 5;
        const int b1 = (m1 & 31) + r;
        #pragma unroll
        for (int nt = 0; nt < 2; nt++) {
            wmma::store_matrix_sync(myscr, acc[mt][nt], 20, wmma::mem_row_major);
            __syncwarp();
            #pragma unroll
            for (int q = 0; q < 8; q++) {
                const int cc  = ch * 8 + q;
                const int col = col0 + wn * 32 + nt * 16 + cc;
                out[((size_t)t1 * G4 + col) * 32 + b1] =
                    myscr[r * 20 + cc] + __ldg(&bias[col]);
            }
            __syncwarp();
        }
    }
}

/* ------------------------------------------------------------------ */
/* WMMA persistent LSTM recurrence, register-resident weights,        */
/* 3 PARALLEL accumulator chains (hh/hl/lh) to break the 48-deep mma  */
/* dependency chain, and the redundant mid-step __syncthreads removed */
/* (scr region does not alias hA; post-scr sync orders next staging). */
/* ------------------------------------------------------------------ */
#define LDA 40
#define LDB 520
#define OFF_HAL 40960
#define OFF_SCR 81920
#define REC_SMEM 92160

__global__ void __launch_bounds__(256, 1)
lstm_rec_wmma(const float* __restrict__ xgF, const float* __restrict__ xgB,
              const __nv_bfloat16* __restrict__ WFh, const __nv_bfloat16* __restrict__ WFl,
              const __nv_bfloat16* __restrict__ WBh, const __nv_bfloat16* __restrict__ WBl,
              __nv_bfloat16* __restrict__ oAh, __nv_bfloat16* __restrict__ oAl,
              float* __restrict__ outf, int writeSplit)
{
    extern __shared__ char smraw[];
    __nv_bfloat16* sWh = (__nv_bfloat16*)smraw;
    __nv_bfloat16* sWl = (__nv_bfloat16*)(smraw + 33280);
    __nv_bfloat16* hAh = (__nv_bfloat16*)smraw;               /* [512][40] */
    __nv_bfloat16* hAl = (__nv_bfloat16*)(smraw + OFF_HAL);   /* [512][40] */
    float*         scr = (float*)(smraw + OFF_SCR);           /* 8 x 320   */

    const int tid = threadIdx.x;
    const int dir = blockIdx.x >> 6;
    const int dd  = blockIdx.x & 63;
    const int wl  = tid >> 5;
    const int b   = tid & 31;
    const int hid = dd * 8 + wl;

    const float* xg = dir ? xgB : xgF;
    const __nv_bfloat16* Wh = dir ? WBh : WFh;
    const __nv_bfloat16* Wl = dir ? WBl : WFl;

    /* phase 1: W rows -> SMEM */
    {
        const uint4* srcH = (const uint4*)(Wh + (size_t)dd * 32 * H_);
        const uint4* srcL = (const uint4*)(Wl + (size_t)dd * 32 * H_);
        for (int i = tid; i < 2048; i += 256) {
            int r  = i >> 6;
            int ch = i & 63;
            ((uint4*)sWh)[r * 65 + ch] = srcH[i];
            ((uint4*)sWl)[r * 65 + ch] = srcL[i];
        }
    }
    __syncthreads();

    const int p  = wl >> 1;
    const int mt = p >> 1;
    const int nt = p & 1;
    const int q  = wl & 1;

    wmma::fragment<wmma::matrix_b, 16, 16, 16, __nv_bfloat16,
                   wmma::col_major> fbh[16], fbl[16];
    #pragma unroll
    for (int kt = 0; kt < 16; kt++) {
        const int ko = (q * 16 + kt) * 16;
        wmma::load_matrix_sync(fbh[kt], sWh + nt * 16 * LDB + ko, LDB);
        wmma::load_matrix_sync(fbl[kt], sWl + nt * 16 * LDB + ko, LDB);
    }
    __syncthreads();

    const __nv_bfloat16* pAh = hAh + mt * 16;
    const __nv_bfloat16* pAl = hAl + mt * 16;

    float c = 0.0f;

    const int t_first = dir ? (T_ - 1) : 0;
    const float* xr0 = xg + ((size_t)t_first * G4 + hid) * 32 + b;
    float p0 = xr0[0 * H_ * 32];
    float p1 = xr0[1 * H_ * 32];
    float p2 = xr0[2 * H_ * 32];
    float p3 = xr0[3 * H_ * 32];

    for (int s = 0; s < T_; s++) {
        const int t = dir ? (T_ - 1 - s) : s;
        float a0 = p0, a1 = p1, a2 = p2, a3 = p3;

        if (s > 0) {
            const int par = (s - 1) & 1;
            const uint4* srcH = (const uint4*)g_hbfH[dir][par];
            const uint4* srcL = (const uint4*)g_hbfL[dir][par];
            for (int i = tid; i < 2048; i += 256) {
                int k  = i >> 2;
                int ch = i & 3;
                ((uint4*)hAh)[k * 5 + ch] = __ldcg(srcH + i);
                ((uint4*)hAl)[k * 5 + ch] = __ldcg(srcL + i);
            }
            __syncthreads();

            /* 3 independent accumulator chains: hh / hl / lh          */
            wmma::fragment<wmma::accumulator, 16, 16, 16, float> f0, f1, f2;
            wmma::fill_fragment(f0, 0.0f);
            wmma::fill_fragment(f1, 0.0f);
            wmma::fill_fragment(f2, 0.0f);
            #pragma unroll
            for (int kt = 0; kt < 16; kt++) {
                const int ko = (q * 16 + kt) * 16;
                wmma::fragment<wmma::matrix_a, 16, 16, 16, __nv_bfloat16,
                               wmma::col_major> fah, fal;
                wmma::load_matrix_sync(fah, pAh + (size_t)ko * LDA, LDA);
                wmma::load_matrix_sync(fal, pAl + (size_t)ko * LDA, LDA);
                wmma::mma_sync(f0, fah, fbh[kt], f0);
                wmma::mma_sync(f1, fah, fbl[kt], f1);
                wmma::mma_sync(f2, fal, fbh[kt], f2);
            }
            #pragma unroll
            for (int e = 0; e < f0.num_elements; e++)
                f0.x[e] += f1.x[e] + f2.x[e];

            wmma::store_matrix_sync(scr + wl * 320, f0, 20, wmma::mem_row_major);
            __syncthreads();

            const int mt2 = b >> 4;
            const int rr  = b & 15;
            #pragma unroll
            for (int g = 0; g < 4; g++) {
                const int p2 = mt2 * 2 + (g >> 1);
                const int cc = rr * 20 + (g & 1) * 8 + wl;
                float pa = scr[(p2 * 2 + 0) * 320 + cc]
                         + scr[(p2 * 2 + 1) * 320 + cc];
                if      (g == 0) a0 += pa;
                else if (g == 1) a1 += pa;
                else if (g == 2) a2 += pa;
                else             a3 += pa;
            }
        }

        float ig = sigmoidf_(a0);
        float fg = sigmoidf_(a1);
        float gg = tanhf(a2);
        float og = sigmoidf_(a3);
        c = fg * c + ig * gg;
        float h = og * tanhf(c);

        __nv_bfloat16 hh, hl;
        bf16_split(h, hh, hl);
        const int par = s & 1;
        g_hbfH[dir][par][hid * 32 + b] = hh;
        g_hbfL[dir][par][hid * 32 + b] = hl;

        if (writeSplit) {
            size_t oi = ((size_t)(t * B_ + b)) * (2 * H_) + dir * H_ + hid;
            oAh[oi] = hh;
            oAl[oi] = hl;
        } else {
            outf[(size_t)(b * T_ + t) * (2 * H_) + dir * H_ + hid] = h;
        }

        if (s != T_ - 1) {
            const int tn = dir ? (T_ - 2 - s) : (s + 1);
            const float* xr = xg + ((size_t)tn * G4 + hid) * 32 + b;
            p0 = xr[0 * H_ * 32];
            p1 = xr[1 * H_ * 32];
            p2 = xr[2 * H_ * 32];
            p3 = xr[3 * H_ * 32];
            grid_barrier_dir(dir);
        }
    }
}

/* ------------------------------------------------------------------ */
/* Host launcher                                                      */
/* ------------------------------------------------------------------ */
extern "C" void kernel_launch(void* const* d_in, const int* in_sizes, int n_in,
                              void* d_out, int out_size)
{
    const float* x     = (const float*)d_in[0];
    const float* wih0f = (const float*)d_in[1];
    const float* whh0f = (const float*)d_in[2];
    const float* b0f   = (const float*)d_in[3];
    const float* wih0b = (const float*)d_in[4];
    const float* whh0b = (const float*)d_in[5];
    const float* b0b   = (const float*)d_in[6];
    const float* wih1f = (const float*)d_in[7];
    const float* whh1f = (const float*)d_in[8];
    const float* b1f   = (const float*)d_in[9];
    const float* wih1b = (const float*)d_in[10];
    const float* whh1b = (const float*)d_in[11];
    const float* b1b   = (const float*)d_in[12];

    float *xgF, *xgB;
    __nv_bfloat16 *ah0, *al0, *ah1, *al1, *wsp0, *wsp1, *wpkH, *wpkL;
    cudaGetSymbolAddress((void**)&xgF,  g_xgF);
    cudaGetSymbolAddress((void**)&xgB,  g_xgB);
    cudaGetSymbolAddress((void**)&ah0,  g_Ah0);
    cudaGetSymbolAddress((void**)&al0,  g_Al0);
    cudaGetSymbolAddress((void**)&ah1,  g_Ah1);
    cudaGetSymbolAddress((void**)&al1,  g_Al1);
    cudaGetSymbolAddress((void**)&wsp0, g_Wsp0);
    cudaGetSymbolAddress((void**)&wsp1, g_Wsp1);
    cudaGetSymbolAddress((void**)&wpkH, g_WpkH);
    cudaGetSymbolAddress((void**)&wpkL, g_WpkL);

    const size_t WS0  = (size_t)G4 * 512;
    const size_t WS1  = (size_t)G4 * 1024;
    const size_t WPK  = (size_t)G4 * H_;
    const int GEMM_SMEM = 49152 + 8 * 320 * 4;
    cudaFuncSetAttribute(lstm_rec_wmma,
                         cudaFuncAttributeMaxDynamicSharedMemorySize, REC_SMEM);
    cudaFuncSetAttribute(gemm_wmma_kernel,
                         cudaFuncAttributeMaxDynamicSharedMemorySize, GEMM_SMEM);

    dim3 tb(32, 8);
    dim3 gg(G4 / 128, 8192 / 128);

    pack_whh4<<<dim3(64, 16, 4), tb>>>(whh0f, whh0b, whh1f, whh1b);          /*0*/
    split_x_kernel<<<16384, 256>>>(x, ah0, al0);                             /*1*/
    transpose_split_w<<<dim3(64, 16), tb>>>(wih0f, wsp0 + 0 * WS0,
                                            wsp0 + 1 * WS0, 512);            /*2*/
    gemm_wmma_kernel<<<gg, 256, GEMM_SMEM>>>(ah0, al0,
        wsp0 + 0 * WS0, wsp0 + 1 * WS0, b0f, xgF, 512);                      /*3*/
    transpose_split_w<<<dim3(64, 16), tb>>>(wih0b, wsp0 + 2 * WS0,
                                            wsp0 + 3 * WS0, 512);            /*4*/
    gemm_wmma_kernel<<<gg, 256, GEMM_SMEM>>>(ah0, al0,
        wsp0 + 2 * WS0, wsp0 + 3 * WS0, b0b, xgB, 512);                      /*5*/
    lstm_rec_wmma<<<NREC_CTAS, 256, REC_SMEM>>>(
        xgF, xgB,
        wpkH + 0 * WPK, wpkL + 0 * WPK,
        wpkH + 1 * WPK, wpkL + 1 * WPK,
        ah1, al1, nullptr, 1);                                               /*6*/
    transpose_split_w<<<dim3(64, 32), tb>>>(wih1f, wsp1 + 0 * WS1,
                                            wsp1 + 1 * WS1, 1024);           /*7*/
    transpose_split_w<<<dim3(64, 32), tb>>>(wih1b, wsp1 + 2 * WS1,
                                            wsp1 + 3 * WS1, 1024);           /*8*/
    gemm_wmma_kernel<<<gg, 256, GEMM_SMEM>>>(ah1, al1,
        wsp1 + 0 * WS1, wsp1 + 1 * WS1, b1f, xgF, 1024);                     /*9*/
    gemm_wmma_kernel<<<gg, 256, GEMM_SMEM>>>(ah1, al1,
        wsp1 + 2 * WS1, wsp1 + 3 * WS1, b1b, xgB, 1024);                     /*10*/
    lstm_rec_wmma<<<NREC_CTAS, 256, REC_SMEM>>>(
        xgF, xgB,
        wpkH + 2 * WPK, wpkL + 2 * WPK,
        wpkH + 3 * WPK, wpkL + 3 * WPK,
        nullptr, nullptr, (float*)d_out, 0);                                 /*11*/
}

// round 15
// speedup vs baseline: 2.7150x; 1.0680x over previous
#include <cuda_runtime.h>
#include <cuda_bf16.h>
#include <mma.h>
#include <math.h>
#include <stdint.h>

using namespace nvcuda;

#define B_   32
#define T_   256
#define IN_  512
#define H_   512
#define G4   2048   /* 4*H */
#define NREC_CTAS 128

/* ------------------------------------------------------------------ */
/* Static device scratch                                              */
/* ------------------------------------------------------------------ */
__device__ float g_xgF[(size_t)T_ * B_ * G4];          /* 64 MB, [t][col][b] */
__device__ float g_xgB[(size_t)T_ * B_ * G4];          /* 64 MB, [t][col][b] */
__device__ unsigned g_barCount[2][32];
__device__ unsigned g_barGen[2][32];

/* recurrent h state, bf16 hi/lo, layout [k=hid][b], double-buffered  */
__device__ __nv_bfloat16 g_hbfH[2][2][H_ * B_];
__device__ __nv_bfloat16 g_hbfL[2][2][H_ * B_];

/* bf16 hi/lo split operands for the tensor-core input GEMMs */
__device__ __nv_bfloat16 g_Ah0[(size_t)8192 * 512];
__device__ __nv_bfloat16 g_Al0[(size_t)8192 * 512];
__device__ __nv_bfloat16 g_Ah1[(size_t)8192 * 1024];
__device__ __nv_bfloat16 g_Al1[(size_t)8192 * 1024];
__device__ __nv_bfloat16 g_Wsp0[2][2][(size_t)G4 * 512];
__device__ __nv_bfloat16 g_Wsp1[2][2][(size_t)G4 * 1024];

/* packed recurrent weights: [layer*2+dir][hi/lo][col'=dd*32+g*8+j][k] */
__device__ __nv_bfloat16 g_WpkH[4][(size_t)G4 * H_];
__device__ __nv_bfloat16 g_WpkL[4][(size_t)G4 * H_];

/* ------------------------------------------------------------------ */
/* Per-direction grid barrier. PROVEN R12 atomic protocol, but the    */
/* release fence is hoisted to tid 0 only (after __syncthreads, so it */
/* is cumulative over the CTA's writes — the CG grid-sync pattern).   */
/* The 2x256 per-thread MEMBAR.GPU per step are gone. Acquire side:   */
/* volatile gen read + __syncthreads; all cross-CTA data reads use    */
/* __ldcg (L2 coherence point), so no trailing fence is needed.       */
/* ------------------------------------------------------------------ */
__device__ __forceinline__ void grid_barrier_dir(int dir)
{
    __syncthreads();
    if (threadIdx.x == 0) {
        __threadfence();              /* cumulative release for the CTA  */
        unsigned gen = *((volatile unsigned*)&g_barGen[dir][0]);
        unsigned arrived = atomicAdd(&g_barCount[dir][0], 1u);
        if (arrived == (NREC_CTAS / 2) - 1) {
            atomicExch(&g_barCount[dir][0], 0u);
            __threadfence();          /* order reset before release      */
            atomicAdd(&g_barGen[dir][0], 1u);
        } else {
            while (*((volatile unsigned*)&g_barGen[dir][0]) == gen) {
                __nanosleep(64);
            }
        }
    }
    __syncthreads();
}

__device__ __forceinline__ float sigmoidf_(float x)
{
    return 1.0f / (1.0f + expf(-x));
}

__device__ __forceinline__ void bf16_split(float v, __nv_bfloat16& h, __nv_bfloat16& l)
{
    h = __float2bfloat16(v);
    l = __float2bfloat16(v - __bfloat162float(h));
}

/* ------------------------------------------------------------------ */
/* x [B][T][IN] fp32 -> Ah/Al [m=t*B+b][k] bf16 hi/lo                 */
/* ------------------------------------------------------------------ */
__global__ void split_x_kernel(const float* __restrict__ x,
                               __nv_bfloat16* __restrict__ Ah,
                               __nv_bfloat16* __restrict__ Al)
{
    int idx = blockIdx.x * blockDim.x + threadIdx.x;
    int m = idx >> 9;
    int k = idx & 511;
    int b = m & 31;
    int t = m >> 5;
    float v = x[((size_t)b * T_ + t) * IN_ + k];
    __nv_bfloat16 h, l;
    bf16_split(v, h, l);
    Ah[idx] = h;
    Al[idx] = l;
}

/* ------------------------------------------------------------------ */
/* W_ih [Din][4H] fp32 -> Wh/Wl [4H][Din] bf16 hi/lo (transposed)     */
/* ------------------------------------------------------------------ */
__global__ void transpose_split_w(const float* __restrict__ W,
                                  __nv_bfloat16* __restrict__ Wh,
                                  __nv_bfloat16* __restrict__ Wl, int Din)
{
    __shared__ float tile[32][33];
    int x  = blockIdx.x * 32 + threadIdx.x;
    int y0 = blockIdx.y * 32;
    #pragma unroll
    for (int i = threadIdx.y; i < 32; i += 8)
        tile[i][threadIdx.x] = W[(size_t)(y0 + i) * G4 + x];
    __syncthreads();
    int k  = y0 + threadIdx.x;
    int n0 = blockIdx.x * 32;
    #pragma unroll
    for (int i = threadIdx.y; i < 32; i += 8) {
        float v = tile[threadIdx.x][i];
        __nv_bfloat16 h, l;
        bf16_split(v, h, l);
        Wh[(size_t)(n0 + i) * Din + k] = h;
        Wl[(size_t)(n0 + i) * Din + k] = l;
    }
}

/* ------------------------------------------------------------------ */
/* Pack all 4 W_hh [H,4H] -> bf16 hi/lo [col'][k], col'=dd*32+g*8+j   */
/* ------------------------------------------------------------------ */
__global__ void pack_whh4(const float* __restrict__ w0,
                          const float* __restrict__ w1,
                          const float* __restrict__ w2,
                          const float* __restrict__ w3)
{
    const int z = blockIdx.z;
    const float* W = (z == 0) ? w0 : (z == 1) ? w1 : (z == 2) ? w2 : w3;
    __nv_bfloat16* Wh = g_WpkH[z];
    __nv_bfloat16* Wl = g_WpkL[z];

    __shared__ float tile[32][33];
    const int tx = threadIdx.x;
    const int k0 = blockIdx.y * 32;
    const int cp0 = blockIdx.x * 32;
    const int c = ((tx >> 3) & 3) * 512 + blockIdx.x * 8 + (tx & 7);
    #pragma unroll
    for (int i = threadIdx.y; i < 32; i += 8)
        tile[i][tx] = W[(size_t)(k0 + i) * G4 + c];
    __syncthreads();
    #pragma unroll
    for (int i = threadIdx.y; i < 32; i += 8) {
        float v = tile[tx][i];
        __nv_bfloat16 h, l;
        bf16_split(v, h, l);
        Wh[(size_t)(cp0 + i) * H_ + k0 + tx] = h;
        Wl[(size_t)(cp0 + i) * H_ + k0 + tx] = l;
    }
}

/* ------------------------------------------------------------------ */
/* WMMA input GEMM, split-bf16 (3 products), fp32 accumulate.         */
/* (unchanged — proven)                                               */
/* ------------------------------------------------------------------ */
__global__ void __launch_bounds__(256)
gemm_wmma_kernel(const __nv_bfloat16* __restrict__ Ah,
                 const __nv_bfloat16* __restrict__ Al,
                 const __nv_bfloat16* __restrict__ Bh,
                 const __nv_bfloat16* __restrict__ Bl,
                 const float* __restrict__ bias,
                 float* __restrict__ out, int Din)
{
    extern __shared__ char smraw[];
    __nv_bfloat16* smb = (__nv_bfloat16*)smraw;
    float* csc = (float*)(smraw + 49152);

    const int tid  = threadIdx.x;
    const int lane = tid & 31;
    const int wid  = tid >> 5;
    const int wm   = wid >> 2;
    const int wn   = wid & 3;
    const int m0   = blockIdx.y * 128;
    const int col0 = blockIdx.x * 128;

    const int lr = tid >> 1;
    const int lh = tid & 1;
    const __nv_bfloat16* gAh = Ah + (size_t)(m0 + lr) * Din + lh * 8;
    const __nv_bfloat16* gAl = Al + (size_t)(m0 + lr) * Din + lh * 8;
    const __nv_bfloat16* gBh = Bh + (size_t)(col0 + lr) * Din + lh * 8;
    const __nv_bfloat16* gBl = Bl + (size_t)(col0 + lr) * Din + lh * 8;
    const int soff = lr * 24 + lh * 8;

    wmma::fragment<wmma::accumulator, 16, 16, 16, float> acc[4][2];
    #pragma unroll
    for (int i = 0; i < 4; i++)
        #pragma unroll
        for (int j = 0; j < 2; j++)
            wmma::fill_fragment(acc[i][j], 0.0f);

    uint4 rAh = *(const uint4*)gAh;
    uint4 rAl = *(const uint4*)gAl;
    uint4 rBh = *(const uint4*)gBh;
    uint4 rBl = *(const uint4*)gBl;

    *(uint4*)(smb + 0 * 12288 + 0 * 3072 + soff) = rAh;
    *(uint4*)(smb + 0 * 12288 + 1 * 3072 + soff) = rAl;
    *(uint4*)(smb + 0 * 12288 + 2 * 3072 + soff) = rBh;
    *(uint4*)(smb + 0 * 12288 + 3 * 3072 + soff) = rBl;
    __syncthreads();

    const int Nk = Din >> 4;
    for (int kt = 0; kt < Nk; kt++) {
        const int cur = kt & 1;
        const int nxt = cur ^ 1;

        if (kt + 1 < Nk) {
            const int ko = (kt + 1) << 4;
            rAh = *(const uint4*)(gAh + ko);
            rAl = *(const uint4*)(gAl + ko);
            rBh = *(const uint4*)(gBh + ko);
            rBl = *(const uint4*)(gBl + ko);
        }

        const __nv_bfloat16* sAh = smb + cur * 12288;
        const __nv_bfloat16* sAl = sAh + 3072;
        const __nv_bfloat16* sBh = sAh + 6144;
        const __nv_bfloat16* sBl = sAh + 9216;

        wmma::fragment<wmma::matrix_b, 16, 16, 16, __nv_bfloat16,
                       wmma::col_major> fbh[2], fbl[2];
        #pragma unroll
        for (int nt = 0; nt < 2; nt++) {
            const int nl = wn * 32 + nt * 16;
            wmma::load_matrix_sync(fbh[nt], sBh + nl * 24, 24);
            wmma::load_matrix_sync(fbl[nt], sBl + nl * 24, 24);
        }

        #pragma unroll
        for (int mt = 0; mt < 4; mt++) {
            const int ml = wm * 64 + mt * 16;
            wmma::fragment<wmma::matrix_a, 16, 16, 16, __nv_bfloat16,
                           wmma::row_major> fah, fal;
            wmma::load_matrix_sync(fah, sAh + ml * 24, 24);
            wmma::load_matrix_sync(fal, sAl + ml * 24, 24);
            #pragma unroll
            for (int nt = 0; nt < 2; nt++) {
                wmma::mma_sync(acc[mt][nt], fah, fbh[nt], acc[mt][nt]);
                wmma::mma_sync(acc[mt][nt], fah, fbl[nt], acc[mt][nt]);
                wmma::mma_sync(acc[mt][nt], fal, fbh[nt], acc[mt][nt]);
            }
        }

        if (kt + 1 < Nk) {
            *(uint4*)(smb + nxt * 12288 + 0 * 3072 + soff) = rAh;
            *(uint4*)(smb + nxt * 12288 + 1 * 3072 + soff) = rAl;
            *(uint4*)(smb + nxt * 12288 + 2 * 3072 + soff) = rBh;
            *(uint4*)(smb + nxt * 12288 + 3 * 3072 + soff) = rBl;
        }
        __syncthreads();
    }

    float* myscr = csc + wid * 320;
    const int r  = lane & 15;
    const int ch = lane >> 4;
    #pragma unroll
    for (int mt = 0; mt < 4; mt++) {
        const int m1 = m0 + wm * 64 + mt * 16;
        const int t1 = m1 >> 5;
        const int b1 = (m1 & 31) + r;
        #pragma unroll
        for (int nt = 0; nt < 2; nt++) {
            wmma::store_matrix_sync(myscr, acc[mt][nt], 20, wmma::mem_row_major);
            __syncwarp();
            #pragma unroll
            for (int q = 0; q < 8; q++) {
                const int cc  = ch * 8 + q;
                const int col = col0 + wn * 32 + nt * 16 + cc;
                out[((size_t)t1 * G4 + col) * 32 + b1] =
                    myscr[r * 20 + cc] + __ldg(&bias[col]);
            }
            __syncwarp();
        }
    }
}

/* ------------------------------------------------------------------ */
/* WMMA persistent LSTM recurrence, register-resident weights,        */
/* 3 parallel accumulator chains, low-fence atomic barrier.           */
/* ------------------------------------------------------------------ */
#define LDA 40
#define LDB 520
#define OFF_HAL 40960
#define OFF_SCR 81920
#define REC_SMEM 92160

__global__ void __launch_bounds__(256, 1)
lstm_rec_wmma(const float* __restrict__ xgF, const float* __restrict__ xgB,
              const __nv_bfloat16* __restrict__ WFh, const __nv_bfloat16* __restrict__ WFl,
              const __nv_bfloat16* __restrict__ WBh, const __nv_bfloat16* __restrict__ WBl,
              __nv_bfloat16* __restrict__ oAh, __nv_bfloat16* __restrict__ oAl,
              float* __restrict__ outf, int writeSplit)
{
    extern __shared__ char smraw[];
    __nv_bfloat16* sWh = (__nv_bfloat16*)smraw;
    __nv_bfloat16* sWl = (__nv_bfloat16*)(smraw + 33280);
    __nv_bfloat16* hAh = (__nv_bfloat16*)smraw;               /* [512][40] */
    __nv_bfloat16* hAl = (__nv_bfloat16*)(smraw + OFF_HAL);   /* [512][40] */
    float*         scr = (float*)(smraw + OFF_SCR);           /* 8 x 320   */

    const int tid = threadIdx.x;
    const int dir = blockIdx.x >> 6;
    const int dd  = blockIdx.x & 63;
    const int wl  = tid >> 5;
    const int b   = tid & 31;
    const int hid = dd * 8 + wl;

    const float* xg = dir ? xgB : xgF;
    const __nv_bfloat16* Wh = dir ? WBh : WFh;
    const __nv_bfloat16* Wl = dir ? WBl : WFl;

    /* phase 1: W rows -> SMEM */
    {
        const uint4* srcH = (const uint4*)(Wh + (size_t)dd * 32 * H_);
        const uint4* srcL = (const uint4*)(Wl + (size_t)dd * 32 * H_);
        for (int i = tid; i < 2048; i += 256) {
            int r  = i >> 6;
            int ch = i & 63;
            ((uint4*)sWh)[r * 65 + ch] = srcH[i];
            ((uint4*)sWl)[r * 65 + ch] = srcL[i];
        }
    }
    __syncthreads();

    const int p  = wl >> 1;
    const int mt = p >> 1;
    const int nt = p & 1;
    const int q  = wl & 1;

    wmma::fragment<wmma::matrix_b, 16, 16, 16, __nv_bfloat16,
                   wmma::col_major> fbh[16], fbl[16];
    #pragma unroll
    for (int kt = 0; kt < 16; kt++) {
        const int ko = (q * 16 + kt) * 16;
        wmma::load_matrix_sync(fbh[kt], sWh + nt * 16 * LDB + ko, LDB);
        wmma::load_matrix_sync(fbl[kt], sWl + nt * 16 * LDB + ko, LDB);
    }
    __syncthreads();

    const __nv_bfloat16* pAh = hAh + mt * 16;
    const __nv_bfloat16* pAl = hAl + mt * 16;

    float c = 0.0f;

    const int t_first = dir ? (T_ - 1) : 0;
    const float* xr0 = xg + ((size_t)t_first * G4 + hid) * 32 + b;
    float p0 = xr0[0 * H_ * 32];
    float p1 = xr0[1 * H_ * 32];
    float p2 = xr0[2 * H_ * 32];
    float p3 = xr0[3 * H_ * 32];

    for (int s = 0; s < T_; s++) {
        const int t = dir ? (T_ - 1 - s) : s;
        float a0 = p0, a1 = p1, a2 = p2, a3 = p3;

        if (s > 0) {
            const int par = (s - 1) & 1;
            const uint4* srcH = (const uint4*)g_hbfH[dir][par];
            const uint4* srcL = (const uint4*)g_hbfL[dir][par];
            for (int i = tid; i < 2048; i += 256) {
                int k  = i >> 2;
                int ch = i & 3;
                ((uint4*)hAh)[k * 5 + ch] = __ldcg(srcH + i);
                ((uint4*)hAl)[k * 5 + ch] = __ldcg(srcL + i);
            }
            __syncthreads();

            wmma::fragment<wmma::accumulator, 16, 16, 16, float> f0, f1, f2;
            wmma::fill_fragment(f0, 0.0f);
            wmma::fill_fragment(f1, 0.0f);
            wmma::fill_fragment(f2, 0.0f);
            #pragma unroll
            for (int kt = 0; kt < 16; kt++) {
                const int ko = (q * 16 + kt) * 16;
                wmma::fragment<wmma::matrix_a, 16, 16, 16, __nv_bfloat16,
                               wmma::col_major> fah, fal;
                wmma::load_matrix_sync(fah, pAh + (size_t)ko * LDA, LDA);
                wmma::load_matrix_sync(fal, pAl + (size_t)ko * LDA, LDA);
                wmma::mma_sync(f0, fah, fbh[kt], f0);
                wmma::mma_sync(f1, fah, fbl[kt], f1);
                wmma::mma_sync(f2, fal, fbh[kt], f2);
            }
            #pragma unroll
            for (int e = 0; e < f0.num_elements; e++)
                f0.x[e] += f1.x[e] + f2.x[e];

            wmma::store_matrix_sync(scr + wl * 320, f0, 20, wmma::mem_row_major);
            __syncthreads();

            const int mt2 = b >> 4;
            const int rr  = b & 15;
            #pragma unroll
            for (int g = 0; g < 4; g++) {
                const int p2 = mt2 * 2 + (g >> 1);
                const int cc = rr * 20 + (g & 1) * 8 + wl;
                float pa = scr[(p2 * 2 + 0) * 320 + cc]
                         + scr[(p2 * 2 + 1) * 320 + cc];
                if      (g == 0) a0 += pa;
                else if (g == 1) a1 += pa;
                else if (g == 2) a2 += pa;
                else             a3 += pa;
            }
        }

        float ig = sigmoidf_(a0);
        float fg = sigmoidf_(a1);
        float gg = tanhf(a2);
        float og = sigmoidf_(a3);
        c = fg * c + ig * gg;
        float h = og * tanhf(c);

        __nv_bfloat16 hh, hl;
        bf16_split(h, hh, hl);
        const int par = s & 1;
        g_hbfH[dir][par][hid * 32 + b] = hh;
        g_hbfL[dir][par][hid * 32 + b] = hl;

        if (writeSplit) {
            size_t oi = ((size_t)(t * B_ + b)) * (2 * H_) + dir * H_ + hid;
            oAh[oi] = hh;
            oAl[oi] = hl;
        } else {
            outf[(size_t)(b * T_ + t) * (2 * H_) + dir * H_ + hid] = h;
        }

        if (s != T_ - 1) {
            const int tn = dir ? (T_ - 2 - s) : (s + 1);
            const float* xr = xg + ((size_t)tn * G4 + hid) * 32 + b;
            p0 = xr[0 * H_ * 32];
            p1 = xr[1 * H_ * 32];
            p2 = xr[2 * H_ * 32];
            p3 = xr[3 * H_ * 32];
            grid_barrier_dir(dir);
        }
    }
}

/* ------------------------------------------------------------------ */
/* Host launcher                                                      */
/* ------------------------------------------------------------------ */
extern "C" void kernel_launch(void* const* d_in, const int* in_sizes, int n_in,
                              void* d_out, int out_size)
{
    const float* x     = (const float*)d_in[0];
    const float* wih0f = (const float*)d_in[1];
    const float* whh0f = (const float*)d_in[2];
    const float* b0f   = (const float*)d_in[3];
    const float* wih0b = (const float*)d_in[4];
    const float* whh0b = (const float*)d_in[5];
    const float* b0b   = (const float*)d_in[6];
    const float* wih1f = (const float*)d_in[7];
    const float* whh1f = (const float*)d_in[8];
    const float* b1f   = (const float*)d_in[9];
    const float* wih1b = (const float*)d_in[10];
    const float* whh1b = (const float*)d_in[11];
    const float* b1b   = (const float*)d_in[12];

    float *xgF, *xgB;
    __nv_bfloat16 *ah0, *al0, *ah1, *al1, *wsp0, *wsp1, *wpkH, *wpkL;
    cudaGetSymbolAddress((void**)&xgF,  g_xgF);
    cudaGetSymbolAddress((void**)&xgB,  g_xgB);
    cudaGetSymbolAddress((void**)&ah0,  g_Ah0);
    cudaGetSymbolAddress((void**)&al0,  g_Al0);
    cudaGetSymbolAddress((void**)&ah1,  g_Ah1);
    cudaGetSymbolAddress((void**)&al1,  g_Al1);
    cudaGetSymbolAddress((void**)&wsp0, g_Wsp0);
    cudaGetSymbolAddress((void**)&wsp1, g_Wsp1);
    cudaGetSymbolAddress((void**)&wpkH, g_WpkH);
    cudaGetSymbolAddress((void**)&wpkL, g_WpkL);

    const size_t WS0  = (size_t)G4 * 512;
    const size_t WS1  = (size_t)G4 * 1024;
    const size_t WPK  = (size_t)G4 * H_;
    const int GEMM_SMEM = 49152 + 8 * 320 * 4;
    cudaFuncSetAttribute(lstm_rec_wmma,
                         cudaFuncAttributeMaxDynamicSharedMemorySize, REC_SMEM);
    cudaFuncSetAttribute(gemm_wmma_kernel,
                         cudaFuncAttributeMaxDynamicSharedMemorySize, GEMM_SMEM);

    dim3 tb(32, 8);
    dim3 gg(G4 / 128, 8192 / 128);

    pack_whh4<<<dim3(64, 16, 4), tb>>>(whh0f, whh0b, whh1f, whh1b);          /*0*/
    split_x_kernel<<<16384, 256>>>(x, ah0, al0);                             /*1*/
    transpose_split_w<<<dim3(64, 16), tb>>>(wih0f, wsp0 + 0 * WS0,
                                            wsp0 + 1 * WS0, 512);            /*2*/
    gemm_wmma_kernel<<<gg, 256, GEMM_SMEM>>>(ah0, al0,
        wsp0 + 0 * WS0, wsp0 + 1 * WS0, b0f, xgF, 512);                      /*3*/
    transpose_split_w<<<dim3(64, 16), tb>>>(wih0b, wsp0 + 2 * WS0,
                                            wsp0 + 3 * WS0, 512);            /*4*/
    gemm_wmma_kernel<<<gg, 256, GEMM_SMEM>>>(ah0, al0,
        wsp0 + 2 * WS0, wsp0 + 3 * WS0, b0b, xgB, 512);                      /*5*/
    lstm_rec_wmma<<<NREC_CTAS, 256, REC_SMEM>>>(
        xgF, xgB,
        wpkH + 0 * WPK, wpkL + 0 * WPK,
        wpkH + 1 * WPK, wpkL + 1 * WPK,
        ah1, al1, nullptr, 1);                                               /*6*/
    transpose_split_w<<<dim3(64, 32), tb>>>(wih1f, wsp1 + 0 * WS1,
                                            wsp1 + 1 * WS1, 1024);           /*7*/
    transpose_split_w<<<dim3(64, 32), tb>>>(wih1b, wsp1 + 2 * WS1,
                                            wsp1 + 3 * WS1, 1024);           /*8*/
    gemm_wmma_kernel<<<gg, 256, GEMM_SMEM>>>(ah1, al1,
        wsp1 + 0 * WS1, wsp1 + 1 * WS1, b1f, xgF, 1024);                     /*9*/
    gemm_wmma_kernel<<<gg, 256, GEMM_SMEM>>>(ah1, al1,
        wsp1 + 2 * WS1, wsp1 + 3 * WS1, b1b, xgB, 1024);                     /*10*/
    lstm_rec_wmma<<<NREC_CTAS, 256, REC_SMEM>>>(
        xgF, xgB,
        wpkH + 2 * WPK, wpkL + 2 * WPK,
        wpkH + 3 * WPK, wpkL + 3 * WPK,
        nullptr, nullptr, (float*)d_out, 0);                                 /*11*/
}